// round 9
// baseline (speedup 1.0000x reference)
#include <cuda_runtime.h>
#include <cuda_bf16.h>
#include <cstdint>

#define NN     50000
#define DD     128
#define KNB    16
#define NTILES 1563    // ceil(NN/32)
#define NSM    148

// ------------------------- global scratch -----------------------------------
__device__ float         g_eh[(size_t)NN * DD];
__device__ float         g_et[(size_t)NN * DD];
__device__ __nv_bfloat16 g_uh[(size_t)NN * DD];
__device__ __nv_bfloat16 g_ul[(size_t)NN * DD];
__device__ __nv_bfloat16 g_vh[(size_t)NN * DD];
__device__ __nv_bfloat16 g_vl[(size_t)NN * DD];

// ------------------------- helpers ------------------------------------------
__device__ __forceinline__ uint32_t smem_u32(const void* p) {
    uint32_t a;
    asm("{ .reg .u64 t; cvta.to.shared.u64 t, %1; cvt.u32.u64 %0, t; }" : "=r"(a) : "l"(p));
    return a;
}
__device__ __forceinline__ uint32_t pack2(__nv_bfloat16 a, __nv_bfloat16 b) {
    __nv_bfloat162 t = __halves2bfloat162(a, b);
    return *(uint32_t*)&t;
}
__device__ __forceinline__ float tanh_hw(float z) {
    float r;
    asm("tanh.approx.f32 %0, %1;" : "=f"(r) : "f"(z));
    return r;
}
__device__ __forceinline__ void cpa16(uint32_t dst, const void* src) {
    asm volatile("cp.async.cg.shared.global [%0], [%1], 16;" :: "r"(dst), "l"(src));
}
#define CP_COMMIT() asm volatile("cp.async.commit_group;")
#define CP_WAIT0()  asm volatile("cp.async.wait_group 0;" ::: "memory")
#define CP_WAIT1()  asm volatile("cp.async.wait_group 1;" ::: "memory")

#define LDSM4(r0, r1, r2, r3, addr) \
    asm volatile("ldmatrix.sync.aligned.m8n8.x4.shared.b16 {%0,%1,%2,%3}, [%4];" \
        : "=r"(r0), "=r"(r1), "=r"(r2), "=r"(r3) : "r"(addr))

#define MMA_BF16(d, a0, a1, a2, a3, b0, b1) \
    asm volatile("mma.sync.aligned.m16n8k16.row.col.f32.bf16.bf16.f32 " \
        "{%0,%1,%2,%3}, {%4,%5,%6,%7}, {%8,%9}, {%0,%1,%2,%3};" \
        : "+f"((d)[0]), "+f"((d)[1]), "+f"((d)[2]), "+f"((d)[3]) \
        : "r"(a0), "r"(a1), "r"(a2), "r"(a3), "r"(b0), "r"(b1))

__device__ __forceinline__ void split4(float4 f, uint2& hv, uint2& lv) {
    __nv_bfloat16 h0 = __float2bfloat16(f.x), h1 = __float2bfloat16(f.y);
    __nv_bfloat16 h2 = __float2bfloat16(f.z), h3 = __float2bfloat16(f.w);
    hv = make_uint2(pack2(h0, h1), pack2(h2, h3));
    lv = make_uint2(
        pack2(__float2bfloat16(f.x - __bfloat162float(h0)), __float2bfloat16(f.y - __bfloat162float(h1))),
        pack2(__float2bfloat16(f.z - __bfloat162float(h2)), __float2bfloat16(f.w - __bfloat162float(h3))));
}

// split a 128x128 fp32 weight matrix into hi/lo bf16 padded smem tiles
__device__ __forceinline__ void w_split_to_smem(const float* W, char* smc,
                                                int hbase, int tid) {
    const float4* W4 = (const float4*)W;
    #pragma unroll
    for (int j = 0; j < 16; j++) {
        int i = tid + j * 256;
        int row = i >> 5, c4 = i & 31;
        uint2 hv, lv;
        split4(W4[i], hv, lv);
        uint32_t off = (uint32_t)(row * 272 + c4 * 8);
        *(uint2*)(smc + hbase + off)         = hv;
        *(uint2*)(smc + hbase + 34816 + off) = lv;
    }
}

// ------------------------- kernel 1: persistent projections -----------------
// CTA handles BOTH matrices per 32-row tile; warp = (matrix, 32-col group),
// 32x32 warp tiles -> 2.0 MACs per LDSM byte.
#define K1_WHH 1024                 // WhH@1024  WhL@35840
#define K1_WTH 70656                // WtH@70656 WtL@105472
#define K1_AEH 140288               // ehH@140288 ehL@148992 etH@157696 etL@166400
#define K1_STG 175104               // fp32 stage: 2 inputs x 32 rows x 512 B
#define K1_SMEM 207872

__global__ void __launch_bounds__(256) k1_proj(
    const float* __restrict__ eh_in, const float* __restrict__ et_in,
    const float* __restrict__ Wh, const float* __restrict__ bh,
    const float* __restrict__ Wt, const float* __restrict__ bt)
{
    extern __shared__ char smc[];
    float* smf = (float*)smc;
    const uint32_t sb = smem_u32(smc);
    const int tid = threadIdx.x, lane = tid & 31, wid = tid >> 5;

    // issue cp.async for first tile (both inputs) into stage
    {
        int n0 = blockIdx.x * 32;
        #pragma unroll
        for (int j = 0; j < 8; j++) {
            int i = tid + j * 256;           // 0..2047: inp = i>>10, row = (i>>5)&31, c4 = i&31
            int inp = i >> 10, row = (i >> 5) & 31, c = i & 31;
            int n = n0 + row;
            uint32_t d = sb + K1_STG + (uint32_t)(inp * 16384 + row * 512 + c * 16);
            const float* in = inp ? et_in : eh_in;
            if (n < NN) cpa16(d, (const char*)in + ((size_t)n * 512 + (size_t)c * 16));
            else        *(uint4*)(smc + K1_STG + inp * 16384 + row * 512 + c * 16) = make_uint4(0u,0u,0u,0u);
        }
        CP_COMMIT();
    }

    if (tid < 128) smf[tid] = bh[tid];
    else           smf[tid] = bt[tid - 128];
    w_split_to_smem(Wh, smc, K1_WHH, tid);   // overlaps in-flight cp.async
    w_split_to_smem(Wt, smc, K1_WTH, tid);

    const int mat   = wid & 1;
    const int ncol0 = (wid >> 1) * 32;
    const uint32_t Ah = sb + K1_AEH + (uint32_t)(mat * 17408);
    const uint32_t Al = Ah + 8704;
    const uint32_t Bh = sb + (mat ? K1_WTH : K1_WHH);
    const uint32_t Bl = Bh + 34816;
    const uint32_t a_off = (uint32_t)(((lane & 7) + ((lane >> 3) & 1) * 8) * 272 + (lane >> 4) * 16);
    const uint32_t b_off = (uint32_t)((ncol0 + (lane >> 4) * 8 + (lane & 7)) * 272 + ((lane >> 3) & 1) * 16);
    float* outp = mat ? g_et : g_eh;
    const float* bias = smf + mat * 128;
    const int r0 = lane >> 2, cs = (lane & 3) * 2;

    for (int tile = blockIdx.x; tile < NTILES; tile += NSM) {
        CP_WAIT0();
        __syncthreads();                     // stage ready; prev GEMM reads of A done

        // convert stage(fp32) -> A hi/lo tiles (both inputs)
        #pragma unroll
        for (int j = 0; j < 8; j++) {
            int i = tid + j * 256;
            int inp = i >> 10, row = (i >> 5) & 31, c4 = i & 31;
            float4 f = *(const float4*)(smc + K1_STG + inp * 16384 + row * 512 + c4 * 16);
            uint2 hv, lv;
            split4(f, hv, lv);
            uint32_t off = (uint32_t)(inp * 17408 + row * 272 + c4 * 8);
            *(uint2*)(smc + K1_AEH + off)        = hv;
            *(uint2*)(smc + K1_AEH + 8704 + off) = lv;
        }
        __syncthreads();

        // issue cp.async for next tile (overlaps GEMM + epilogue)
        {
            int nt = tile + NSM;
            if (nt < NTILES) {
                int n0 = nt * 32;
                #pragma unroll
                for (int j = 0; j < 8; j++) {
                    int i = tid + j * 256;
                    int inp = i >> 10, row = (i >> 5) & 31, c = i & 31;
                    int n = n0 + row;
                    uint32_t d = sb + K1_STG + (uint32_t)(inp * 16384 + row * 512 + c * 16);
                    const float* in = inp ? et_in : eh_in;
                    if (n < NN) cpa16(d, (const char*)in + ((size_t)n * 512 + (size_t)c * 16));
                    else        *(uint4*)(smc + K1_STG + inp * 16384 + row * 512 + c * 16) = make_uint4(0u,0u,0u,0u);
                }
            }
            CP_COMMIT();
        }

        float acc[2][4][4];
        #pragma unroll
        for (int mt = 0; mt < 2; mt++)
            #pragma unroll
            for (int t = 0; t < 4; t++) {
                acc[mt][t][0] = 0.f; acc[mt][t][1] = 0.f;
                acc[mt][t][2] = 0.f; acc[mt][t][3] = 0.f;
            }

        #pragma unroll
        for (int pass = 0; pass < 3; pass++) {
            uint32_t A = ((pass == 2) ? Al : Ah) + a_off;
            uint32_t B = ((pass == 1) ? Bl : Bh) + b_off;
            #pragma unroll
            for (int ks = 0; ks < 8; ks++) {
                uint32_t ka = ks * 32;
                uint32_t a0, a1, a2, a3, a4, a5, a6, a7;
                LDSM4(a0, a1, a2, a3, A + ka);
                LDSM4(a4, a5, a6, a7, A + ka + 16 * 272);
                uint32_t b0, b1, b2, b3, b4, b5, b6, b7;
                LDSM4(b0, b1, b2, b3, B + ka);
                LDSM4(b4, b5, b6, b7, B + ka + 16 * 272);
                MMA_BF16(acc[0][0], a0, a1, a2, a3, b0, b1);
                MMA_BF16(acc[0][1], a0, a1, a2, a3, b2, b3);
                MMA_BF16(acc[0][2], a0, a1, a2, a3, b4, b5);
                MMA_BF16(acc[0][3], a0, a1, a2, a3, b6, b7);
                MMA_BF16(acc[1][0], a4, a5, a6, a7, b0, b1);
                MMA_BF16(acc[1][1], a4, a5, a6, a7, b2, b3);
                MMA_BF16(acc[1][2], a4, a5, a6, a7, b4, b5);
                MMA_BF16(acc[1][3], a4, a5, a6, a7, b6, b7);
            }
        }

        int n0r = tile * 32;
        #pragma unroll
        for (int mt = 0; mt < 2; mt++) {
            #pragma unroll
            for (int t = 0; t < 4; t++) {
                int col = ncol0 + t * 8 + cs;
                float bv0 = bias[col], bv1 = bias[col + 1];
                int na = n0r + mt * 16 + r0, nb2 = na + 8;
                if (na < NN)
                    *(float2*)&outp[(size_t)na * DD + col] =
                        make_float2(acc[mt][t][0] + bv0, acc[mt][t][1] + bv1);
                if (nb2 < NN)
                    *(float2*)&outp[(size_t)nb2 * DD + col] =
                        make_float2(acc[mt][t][2] + bv0, acc[mt][t][3] + bv1);
            }
        }
    }
}

// ------------------------- kernel 2: attention (hw tanh) --------------------
__global__ void __launch_bounds__(256, 3) k2_attn(
    const float* __restrict__ x, const int* __restrict__ tidx,
    const float* __restrict__ tw)
{
    const int tid = threadIdx.x, lane = tid & 31, wid = tid >> 5;
    const int n0 = blockIdx.x * 32;

    #pragma unroll 1
    for (int rr = 0; rr < 4; rr++) {
        const int n = n0 + wid * 4 + rr;
        if (n >= NN) continue;
        float4 eh = ((const float4*)g_eh)[(size_t)n * 32 + lane];
        float4 xr = ((const float4*)x)[(size_t)n * 32 + lane];

        int   ids[KNB];
        float ps[KNB];
        {
            const int4*   ip = (const int4*)(tidx + (size_t)n * KNB);
            const float4* pp = (const float4*)(tw + (size_t)n * KNB);
            #pragma unroll
            for (int j = 0; j < 4; j++) {
                int4 I = ip[j]; float4 P = pp[j];
                ids[4 * j + 0] = I.x; ids[4 * j + 1] = I.y;
                ids[4 * j + 2] = I.z; ids[4 * j + 3] = I.w;
                ps[4 * j + 0] = P.x; ps[4 * j + 1] = P.y;
                ps[4 * j + 2] = P.z; ps[4 * j + 3] = P.w;
            }
        }

        float a0 = 0.f, a1 = 0.f, a2 = 0.f, a3 = 0.f, s = 0.f;
        float4 nv0 = ((const float4*)g_et)[(size_t)ids[0] * 32 + lane];
        float4 nv1 = ((const float4*)g_et)[(size_t)ids[1] * 32 + lane];
        #pragma unroll
        for (int k = 0; k < KNB; k++) {
            float4 cur = nv0;
            nv0 = nv1;
            if (k + 2 < KNB)
                nv1 = ((const float4*)g_et)[(size_t)ids[k + 2] * 32 + lane];
            float p = ps[k], q = 2.0f - p;
            float part;
            part  = cur.x * tanh_hw(fmaf(q, eh.x, p * cur.x));
            part += cur.y * tanh_hw(fmaf(q, eh.y, p * cur.y));
            part += cur.z * tanh_hw(fmaf(q, eh.z, p * cur.z));
            part += cur.w * tanh_hw(fmaf(q, eh.w, p * cur.w));
            #pragma unroll
            for (int o = 16; o >= 1; o >>= 1)
                part += __shfl_xor_sync(0xffffffffu, part, o);
            float e = __expf(part);
            a0 = fmaf(e, cur.x, a0);
            a1 = fmaf(e, cur.y, a1);
            a2 = fmaf(e, cur.z, a2);
            a3 = fmaf(e, cur.w, a3);
            s += e;
        }
        float inv = __fdividef(1.0f, s);
        float e0 = a0 * inv, e1 = a1 * inv, e2 = a2 * inv, e3 = a3 * inv;

        float4 u = make_float4(xr.x + e0, xr.y + e1, xr.z + e2, xr.w + e3);
        float4 v = make_float4(xr.x * e0, xr.y * e1, xr.z * e2, xr.w * e3);
        uint2 uhv, ulv, vhv, vlv;
        split4(u, uhv, ulv);
        split4(v, vhv, vlv);
        ((uint2*)(g_uh + (size_t)n * DD))[lane] = uhv;
        ((uint2*)(g_ul + (size_t)n * DD))[lane] = ulv;
        ((uint2*)(g_vh + (size_t)n * DD))[lane] = vhv;
        ((uint2*)(g_vl + (size_t)n * DD))[lane] = vlv;
    }
}

// ------------------------- kernel 3: persistent GEMMs + LN ------------------
// warp = (matrix U|V, 32-col group), full 32 rows -> 2.0 MACs per LDSM byte.
#define K3_W1H 2048
#define K3_W2H 71680
#define K3_S0  141312
#define K3_S1  176128
#define K3_SMEM 210944

__device__ __forceinline__ void k3_prefetch(int tile, uint32_t stage, int tid) {
    int n0 = tile * 32;
    #pragma unroll
    for (int j = 0; j < 8; j++) {
        int i = tid + j * 256;
        int arr = i >> 9, row = (i >> 4) & 31, c = i & 15;
        int n = n0 + row;
        if (n < NN) {
            const __nv_bfloat16* src = (arr == 0) ? g_uh : (arr == 1) ? g_ul
                                      : (arr == 2) ? g_vh : g_vl;
            cpa16(stage + (uint32_t)(arr * 8704 + row * 272 + c * 16),
                  (const char*)src + ((size_t)n * 256 + (size_t)c * 16));
        }
    }
    CP_COMMIT();
}

__global__ void __launch_bounds__(256) k3_out(
    const float* __restrict__ W1, const float* __restrict__ b1,
    const float* __restrict__ W2, const float* __restrict__ b2,
    const float* __restrict__ gamma, const float* __restrict__ beta,
    float* __restrict__ out)
{
    extern __shared__ char smc[];
    float* smf = (float*)smc;
    const uint32_t sb = smem_u32(smc);
    const int tid = threadIdx.x, lane = tid & 31, wid = tid >> 5;

    k3_prefetch(blockIdx.x, sb + K3_S0, tid);

    if (tid < 128) { smf[tid] = b1[tid];       smf[256 + tid] = gamma[tid]; }
    else           { smf[tid] = b2[tid - 128]; smf[256 + tid] = beta[tid - 128]; }
    w_split_to_smem(W1, smc, K3_W1H, tid);
    w_split_to_smem(W2, smc, K3_W2H, tid);

    const int mat   = wid & 1;                 // 0: U@W1, 1: V@W2
    const int ncol0 = (wid >> 1) * 32;
    const uint32_t Bh = sb + (mat ? K3_W2H : K3_W1H);
    const uint32_t Bl = Bh + 34816;
    const uint32_t a_off = (uint32_t)(((lane & 7) + ((lane >> 3) & 1) * 8) * 272 + (lane >> 4) * 16);
    const uint32_t b_off = (uint32_t)((ncol0 + (lane >> 4) * 8 + (lane & 7)) * 272 + ((lane >> 3) & 1) * 16);
    const int r0 = lane >> 2, cs = (lane & 3) * 2;
    const float* bias = smf + mat * 128;

    float4 gv, bvv;
    gv.x  = smf[256 + lane * 4 + 0]; gv.y  = smf[256 + lane * 4 + 1];
    gv.z  = smf[256 + lane * 4 + 2]; gv.w  = smf[256 + lane * 4 + 3];
    bvv.x = smf[384 + lane * 4 + 0]; bvv.y = smf[384 + lane * 4 + 1];
    bvv.z = smf[384 + lane * 4 + 2]; bvv.w = smf[384 + lane * 4 + 3];

    int cur = 0;
    for (int tile = blockIdx.x; tile < NTILES; tile += NSM) {
        int nt = tile + NSM;
        if (nt < NTILES) k3_prefetch(nt, sb + (cur ? K3_S0 : K3_S1), tid);
        else             CP_COMMIT();
        CP_WAIT1();
        __syncthreads();

        const uint32_t S = sb + (cur ? K3_S1 : K3_S0);
        const uint32_t Ah = S + (uint32_t)(mat * 17408);
        const uint32_t Al = Ah + 8704;

        float acc[2][4][4];
        #pragma unroll
        for (int mt = 0; mt < 2; mt++)
            #pragma unroll
            for (int t = 0; t < 4; t++) {
                acc[mt][t][0] = 0.f; acc[mt][t][1] = 0.f;
                acc[mt][t][2] = 0.f; acc[mt][t][3] = 0.f;
            }

        #pragma unroll
        for (int pass = 0; pass < 3; pass++) {
            uint32_t A = ((pass == 2) ? Al : Ah) + a_off;
            uint32_t B = ((pass == 1) ? Bl : Bh) + b_off;
            #pragma unroll
            for (int ks = 0; ks < 8; ks++) {
                uint32_t ka = ks * 32;
                uint32_t a0, a1, a2, a3, a4, a5, a6, a7;
                LDSM4(a0, a1, a2, a3, A + ka);
                LDSM4(a4, a5, a6, a7, A + ka + 16 * 272);
                uint32_t b0, b1, b2, b3, b4, b5, b6, b7;
                LDSM4(b0, b1, b2, b3, B + ka);
                LDSM4(b4, b5, b6, b7, B + ka + 16 * 272);
                MMA_BF16(acc[0][0], a0, a1, a2, a3, b0, b1);
                MMA_BF16(acc[0][1], a0, a1, a2, a3, b2, b3);
                MMA_BF16(acc[0][2], a0, a1, a2, a3, b4, b5);
                MMA_BF16(acc[0][3], a0, a1, a2, a3, b6, b7);
                MMA_BF16(acc[1][0], a4, a5, a6, a7, b0, b1);
                MMA_BF16(acc[1][1], a4, a5, a6, a7, b2, b3);
                MMA_BF16(acc[1][2], a4, a5, a6, a7, b4, b5);
                MMA_BF16(acc[1][3], a4, a5, a6, a7, b6, b7);
            }
        }
        __syncthreads();   // GEMM reads of stage done -> reuse as hbuf

        float* hb = (float*)(smc + (cur ? K3_S1 : K3_S0));
        // U-warps write leaky(U+b1)
        if (mat == 0) {
            #pragma unroll
            for (int mt = 0; mt < 2; mt++)
                #pragma unroll
                for (int t = 0; t < 4; t++) {
                    int col = ncol0 + t * 8 + cs;
                    float bv0 = bias[col], bv1 = bias[col + 1];
                    #pragma unroll
                    for (int half = 0; half < 2; half++) {
                        int row = mt * 16 + r0 + half * 8;
                        float t1a = acc[mt][t][2 * half + 0] + bv0;
                        float t1b = acc[mt][t][2 * half + 1] + bv1;
                        t1a = (t1a > 0.f) ? t1a : 0.01f * t1a;
                        t1b = (t1b > 0.f) ? t1b : 0.01f * t1b;
                        *(float2*)&hb[row * 132 + col] = make_float2(t1a, t1b);
                    }
                }
        }
        __syncthreads();
        // V-warps add leaky(V+b2)
        if (mat == 1) {
            #pragma unroll
            for (int mt = 0; mt < 2; mt++)
                #pragma unroll
                for (int t = 0; t < 4; t++) {
                    int col = ncol0 + t * 8 + cs;
                    float bv0 = bias[col], bv1 = bias[col + 1];
                    #pragma unroll
                    for (int half = 0; half < 2; half++) {
                        int row = mt * 16 + r0 + half * 8;
                        float t2a = acc[mt][t][2 * half + 0] + bv0;
                        float t2b = acc[mt][t][2 * half + 1] + bv1;
                        t2a = (t2a > 0.f) ? t2a : 0.01f * t2a;
                        t2b = (t2b > 0.f) ? t2b : 0.01f * t2b;
                        float2 old = *(float2*)&hb[row * 132 + col];
                        *(float2*)&hb[row * 132 + col] = make_float2(old.x + t2a, old.y + t2b);
                    }
                }
        }
        __syncthreads();

        int n0r = tile * 32;
        #pragma unroll
        for (int rr = 0; rr < 4; rr++) {
            int rw = wid * 4 + rr;
            int n = n0r + rw;
            float4 h = *(float4*)&hb[rw * 132 + lane * 4];
            float s  = h.x + h.y + h.z + h.w;
            float sq = h.x * h.x + h.y * h.y + h.z * h.z + h.w * h.w;
            #pragma unroll
            for (int o = 16; o >= 1; o >>= 1) {
                s  += __shfl_xor_sync(0xffffffffu, s,  o);
                sq += __shfl_xor_sync(0xffffffffu, sq, o);
            }
            float mu  = s * (1.0f / 128.0f);
            float var = sq * (1.0f / 128.0f) - mu * mu;
            float rs  = rsqrtf(var + 1e-5f);
            if (n < NN) {
                float4 o4;
                o4.x = (h.x - mu) * rs * gv.x + bvv.x;
                o4.y = (h.y - mu) * rs * gv.y + bvv.y;
                o4.z = (h.z - mu) * rs * gv.z + bvv.z;
                o4.w = (h.w - mu) * rs * gv.w + bvv.w;
                ((float4*)out)[(size_t)n * 32 + lane] = o4;
            }
        }
        __syncthreads();
        cur ^= 1;
    }
}

// ---------------------------------------------------------------------------
extern "C" void kernel_launch(void* const* d_in, const int* in_sizes, int n_in,
                              void* d_out, int out_size) {
    const float* x     = (const float*)d_in[0];
    const float* eh_in = (const float*)d_in[1];
    const float* et_in = (const float*)d_in[2];
    const int*   tidx  = (const int*)  d_in[3];
    const float* tw    = (const float*)d_in[4];
    const float* Wh    = (const float*)d_in[5];
    const float* bh    = (const float*)d_in[6];
    const float* Wt    = (const float*)d_in[7];
    const float* bt    = (const float*)d_in[8];
    const float* W1    = (const float*)d_in[9];
    const float* b1    = (const float*)d_in[10];
    const float* W2    = (const float*)d_in[11];
    const float* b2    = (const float*)d_in[12];
    const float* gamma = (const float*)d_in[13];
    const float* beta  = (const float*)d_in[14];
    float* out = (float*)d_out;

    cudaFuncSetAttribute(k1_proj, cudaFuncAttributeMaxDynamicSharedMemorySize, K1_SMEM);
    cudaFuncSetAttribute(k3_out,  cudaFuncAttributeMaxDynamicSharedMemorySize, K3_SMEM);

    k1_proj<<<NSM, 256, K1_SMEM>>>(eh_in, et_in, Wh, bh, Wt, bt);
    k2_attn<<<NTILES, 256>>>(x, tidx, tw);
    k3_out<<<NSM, 256, K3_SMEM>>>(W1, b1, W2, b2, gamma, beta, out);
}

// round 10
// speedup vs baseline: 1.5343x; 1.5343x over previous
#include <cuda_runtime.h>
#include <cuda_bf16.h>
#include <cstdint>

#define NN     50000
#define DD     128
#define KNB    16
#define NTILES 1563    // ceil(NN/32)
#define NSM    148

// ------------------------- global scratch -----------------------------------
__device__ float         g_eh[(size_t)NN * DD];
__device__ float         g_et[(size_t)NN * DD];
__device__ __nv_bfloat16 g_uh[(size_t)NN * DD];
__device__ __nv_bfloat16 g_ul[(size_t)NN * DD];
__device__ __nv_bfloat16 g_vh[(size_t)NN * DD];
__device__ __nv_bfloat16 g_vl[(size_t)NN * DD];

// ------------------------- helpers ------------------------------------------
__device__ __forceinline__ uint32_t smem_u32(const void* p) {
    uint32_t a;
    asm("{ .reg .u64 t; cvta.to.shared.u64 t, %1; cvt.u32.u64 %0, t; }" : "=r"(a) : "l"(p));
    return a;
}
__device__ __forceinline__ uint32_t pack2(__nv_bfloat16 a, __nv_bfloat16 b) {
    __nv_bfloat162 t = __halves2bfloat162(a, b);
    return *(uint32_t*)&t;
}
__device__ __forceinline__ float tanh_hw(float z) {
    float r;
    asm("tanh.approx.f32 %0, %1;" : "=f"(r) : "f"(z));
    return r;
}
__device__ __forceinline__ void cpa16(uint32_t dst, const void* src) {
    asm volatile("cp.async.cg.shared.global [%0], [%1], 16;" :: "r"(dst), "l"(src));
}
#define CP_COMMIT() asm volatile("cp.async.commit_group;")
#define CP_WAIT0()  asm volatile("cp.async.wait_group 0;" ::: "memory")
#define CP_WAIT1()  asm volatile("cp.async.wait_group 1;" ::: "memory")

#define LDSM4(r0, r1, r2, r3, addr) \
    asm volatile("ldmatrix.sync.aligned.m8n8.x4.shared.b16 {%0,%1,%2,%3}, [%4];" \
        : "=r"(r0), "=r"(r1), "=r"(r2), "=r"(r3) : "r"(addr))

#define MMA_BF16(d, a0, a1, a2, a3, b0, b1) \
    asm volatile("mma.sync.aligned.m16n8k16.row.col.f32.bf16.bf16.f32 " \
        "{%0,%1,%2,%3}, {%4,%5,%6,%7}, {%8,%9}, {%0,%1,%2,%3};" \
        : "+f"((d)[0]), "+f"((d)[1]), "+f"((d)[2]), "+f"((d)[3]) \
        : "r"(a0), "r"(a1), "r"(a2), "r"(a3), "r"(b0), "r"(b1))

__device__ __forceinline__ void split4(float4 f, uint2& hv, uint2& lv) {
    __nv_bfloat16 h0 = __float2bfloat16(f.x), h1 = __float2bfloat16(f.y);
    __nv_bfloat16 h2 = __float2bfloat16(f.z), h3 = __float2bfloat16(f.w);
    hv = make_uint2(pack2(h0, h1), pack2(h2, h3));
    lv = make_uint2(
        pack2(__float2bfloat16(f.x - __bfloat162float(h0)), __float2bfloat16(f.y - __bfloat162float(h1))),
        pack2(__float2bfloat16(f.z - __bfloat162float(h2)), __float2bfloat16(f.w - __bfloat162float(h3))));
}

// split a 128x128 fp32 weight matrix into hi/lo bf16 padded smem tiles
__device__ __forceinline__ void w_split_to_smem(const float* W, char* smc,
                                                int hbase, int tid) {
    const float4* W4 = (const float4*)W;
    #pragma unroll
    for (int j = 0; j < 16; j++) {
        int i = tid + j * 256;
        int row = i >> 5, c4 = i & 31;
        uint2 hv, lv;
        split4(W4[i], hv, lv);
        uint32_t off = (uint32_t)(row * 272 + c4 * 8);
        *(uint2*)(smc + hbase + off)         = hv;
        *(uint2*)(smc + hbase + 34816 + off) = lv;
    }
}

// ------------------------- kernel 1: persistent projections -----------------
// one matrix per CTA (grid = 2*NSM), 2 CTAs/SM; input staged via cp.async
#define K1_WH   512
#define K1_WL   (K1_WH + 34816)
#define K1_A    (K1_WL + 34816)     // 70144: Ah, then Al at +8704
#define K1_STG  (K1_A + 17408)      // 87552: fp32 stage, 32 rows x 512 B
#define K1_SMEM (K1_STG + 16384)    // 103936  -> 2 CTAs/SM

__global__ void __launch_bounds__(256, 2) k1_proj(
    const float* __restrict__ eh_in, const float* __restrict__ et_in,
    const float* __restrict__ Wh, const float* __restrict__ bh,
    const float* __restrict__ Wt, const float* __restrict__ bt)
{
    extern __shared__ char smc[];
    float* smf = (float*)smc;
    const uint32_t sb = smem_u32(smc);
    const int tid = threadIdx.x, lane = tid & 31, wid = tid >> 5;
    const int mat = blockIdx.x & 1;
    const int ct0 = blockIdx.x >> 1;

    const float* in   = mat ? et_in : eh_in;
    const float* W    = mat ? Wt : Wh;
    const float* bias = mat ? bt : bh;
    float* outp       = mat ? g_et : g_eh;

    // issue cp.async for first tile into stage
    {
        int n0 = ct0 * 32;
        #pragma unroll
        for (int j = 0; j < 4; j++) {
            int i = tid + j * 256;
            int row = i >> 5, c = i & 31;
            int n = n0 + row;
            uint32_t d = sb + K1_STG + (uint32_t)(row * 512 + c * 16);
            if (n < NN) cpa16(d, (const char*)in + ((size_t)n * 512 + (size_t)c * 16));
            else        *(uint4*)(smc + K1_STG + row * 512 + c * 16) = make_uint4(0u,0u,0u,0u);
        }
        CP_COMMIT();
    }

    if (tid < 128) smf[tid] = bias[tid];
    w_split_to_smem(W, smc, K1_WH, tid);   // overlaps in-flight cp.async

    const uint32_t Ah = sb + K1_A, Al = Ah + 8704;
    const uint32_t Bh = sb + K1_WH, Bl = sb + K1_WL;
    const int nbase = wid * 16;
    const uint32_t a_off = (uint32_t)(((lane & 7) + ((lane >> 3) & 1) * 8) * 272 + (lane >> 4) * 16);
    const uint32_t b_off = (uint32_t)((nbase + (lane >> 4) * 8 + (lane & 7)) * 272 + ((lane >> 3) & 1) * 16);
    const int r0 = lane >> 2, cs = (lane & 3) * 2;

    for (int tile = ct0; tile < NTILES; tile += NSM) {
        CP_WAIT0();
        __syncthreads();

        // convert stage(fp32) -> Ah/Al (split bf16)
        #pragma unroll
        for (int j = 0; j < 4; j++) {
            int i = tid + j * 256;
            int row = i >> 5, c4 = i & 31;
            float4 f = *(const float4*)(smc + K1_STG + row * 512 + c4 * 16);
            uint2 hv, lv;
            split4(f, hv, lv);
            uint32_t off = (uint32_t)(row * 272 + c4 * 8);
            *(uint2*)(smc + K1_A + off)        = hv;
            *(uint2*)(smc + K1_A + 8704 + off) = lv;
        }
        __syncthreads();

        // issue cp.async for next tile (overlaps gemm + epilogue)
        {
            int nt = tile + NSM;
            if (nt < NTILES) {
                int n0 = nt * 32;
                #pragma unroll
                for (int j = 0; j < 4; j++) {
                    int i = tid + j * 256;
                    int row = i >> 5, c = i & 31;
                    int n = n0 + row;
                    uint32_t d = sb + K1_STG + (uint32_t)(row * 512 + c * 16);
                    if (n < NN) cpa16(d, (const char*)in + ((size_t)n * 512 + (size_t)c * 16));
                    else        *(uint4*)(smc + K1_STG + row * 512 + c * 16) = make_uint4(0u,0u,0u,0u);
                }
            }
            CP_COMMIT();
        }

        float acc[2][2][4];
        #pragma unroll
        for (int mt = 0; mt < 2; mt++)
            #pragma unroll
            for (int t = 0; t < 2; t++) {
                acc[mt][t][0] = 0.f; acc[mt][t][1] = 0.f;
                acc[mt][t][2] = 0.f; acc[mt][t][3] = 0.f;
            }

        #pragma unroll
        for (int pass = 0; pass < 3; pass++) {
            uint32_t A = ((pass == 2) ? Al : Ah) + a_off;
            uint32_t B = ((pass == 1) ? Bl : Bh) + b_off;
            #pragma unroll
            for (int ks = 0; ks < 8; ks++) {
                uint32_t ka = ks * 32;
                uint32_t a0, a1, a2, a3, a4, a5, a6, a7;
                LDSM4(a0, a1, a2, a3, A + ka);
                LDSM4(a4, a5, a6, a7, A + ka + 16 * 272);
                uint32_t b0, b1, b2, b3;
                LDSM4(b0, b1, b2, b3, B + ka);
                MMA_BF16(acc[0][0], a0, a1, a2, a3, b0, b1);
                MMA_BF16(acc[0][1], a0, a1, a2, a3, b2, b3);
                MMA_BF16(acc[1][0], a4, a5, a6, a7, b0, b1);
                MMA_BF16(acc[1][1], a4, a5, a6, a7, b2, b3);
            }
        }

        int n0r = tile * 32;
        #pragma unroll
        for (int mt = 0; mt < 2; mt++) {
            #pragma unroll
            for (int t = 0; t < 2; t++) {
                int col = nbase + t * 8 + cs;
                float bv0 = smf[col], bv1 = smf[col + 1];
                int na = n0r + mt * 16 + r0, nb2 = na + 8;
                if (na < NN)
                    *(float2*)&outp[(size_t)na * DD + col] =
                        make_float2(acc[mt][t][0] + bv0, acc[mt][t][1] + bv1);
                if (nb2 < NN)
                    *(float2*)&outp[(size_t)nb2 * DD + col] =
                        make_float2(acc[mt][t][2] + bv0, acc[mt][t][3] + bv1);
            }
        }
    }
}

// ------------------------- kernel 2: attention (hw tanh, depth-3 gather) ----
__global__ void __launch_bounds__(256, 3) k2_attn(
    const float* __restrict__ x, const int* __restrict__ tidx,
    const float* __restrict__ tw)
{
    const int tid = threadIdx.x, lane = tid & 31, wid = tid >> 5;
    const int n0 = blockIdx.x * 32;

    #pragma unroll 1
    for (int rr = 0; rr < 4; rr++) {
        const int n = n0 + wid * 4 + rr;
        if (n >= NN) continue;
        float4 eh = ((const float4*)g_eh)[(size_t)n * 32 + lane];
        float4 xr = ((const float4*)x)[(size_t)n * 32 + lane];

        int   ids[KNB];
        float ps[KNB];
        {
            const int4*   ip = (const int4*)(tidx + (size_t)n * KNB);
            const float4* pp = (const float4*)(tw + (size_t)n * KNB);
            #pragma unroll
            for (int j = 0; j < 4; j++) {
                int4 I = ip[j]; float4 P = pp[j];
                ids[4 * j + 0] = I.x; ids[4 * j + 1] = I.y;
                ids[4 * j + 2] = I.z; ids[4 * j + 3] = I.w;
                ps[4 * j + 0] = P.x; ps[4 * j + 1] = P.y;
                ps[4 * j + 2] = P.z; ps[4 * j + 3] = P.w;
            }
        }

        // online softmax accumulation, depth-3 gather pipeline
        float a0 = 0.f, a1 = 0.f, a2 = 0.f, a3 = 0.f, s = 0.f;
        float4 nv0 = ((const float4*)g_et)[(size_t)ids[0] * 32 + lane];
        float4 nv1 = ((const float4*)g_et)[(size_t)ids[1] * 32 + lane];
        float4 nv2 = ((const float4*)g_et)[(size_t)ids[2] * 32 + lane];
        #pragma unroll
        for (int k = 0; k < KNB; k++) {
            float4 cur = nv0;
            nv0 = nv1;
            nv1 = nv2;
            if (k + 3 < KNB)
                nv2 = ((const float4*)g_et)[(size_t)ids[k + 3] * 32 + lane];
            float p = ps[k], q = 2.0f - p;
            float part;
            part  = cur.x * tanh_hw(fmaf(q, eh.x, p * cur.x));
            part += cur.y * tanh_hw(fmaf(q, eh.y, p * cur.y));
            part += cur.z * tanh_hw(fmaf(q, eh.z, p * cur.z));
            part += cur.w * tanh_hw(fmaf(q, eh.w, p * cur.w));
            #pragma unroll
            for (int o = 16; o >= 1; o >>= 1)
                part += __shfl_xor_sync(0xffffffffu, part, o);
            float e = __expf(part);   // |part| bounded ~25; safe without shift
            a0 = fmaf(e, cur.x, a0);
            a1 = fmaf(e, cur.y, a1);
            a2 = fmaf(e, cur.z, a2);
            a3 = fmaf(e, cur.w, a3);
            s += e;
        }
        float inv = __fdividef(1.0f, s);
        float e0 = a0 * inv, e1 = a1 * inv, e2 = a2 * inv, e3 = a3 * inv;

        float4 u = make_float4(xr.x + e0, xr.y + e1, xr.z + e2, xr.w + e3);
        float4 v = make_float4(xr.x * e0, xr.y * e1, xr.z * e2, xr.w * e3);
        uint2 uhv, ulv, vhv, vlv;
        split4(u, uhv, ulv);
        split4(v, vhv, vlv);
        ((uint2*)(g_uh + (size_t)n * DD))[lane] = uhv;
        ((uint2*)(g_ul + (size_t)n * DD))[lane] = ulv;
        ((uint2*)(g_vh + (size_t)n * DD))[lane] = vhv;
        ((uint2*)(g_vl + (size_t)n * DD))[lane] = vlv;
    }
}

// ------------------------- kernel 3: persistent GEMMs + LN ------------------
#define K3_W1H 2048
#define K3_W2H 71680
#define K3_S0  141312
#define K3_S1  176128
#define K3_SMEM 210944

__device__ __forceinline__ void k3_prefetch(int tile, uint32_t stage, int tid) {
    int n0 = tile * 32;
    #pragma unroll
    for (int j = 0; j < 8; j++) {
        int i = tid + j * 256;
        int arr = i >> 9, row = (i >> 4) & 31, c = i & 15;
        int n = n0 + row;
        if (n < NN) {
            const __nv_bfloat16* src = (arr == 0) ? g_uh : (arr == 1) ? g_ul
                                      : (arr == 2) ? g_vh : g_vl;
            cpa16(stage + (uint32_t)(arr * 8704 + row * 272 + c * 16),
                  (const char*)src + ((size_t)n * 256 + (size_t)c * 16));
        }
    }
    CP_COMMIT();
}

__global__ void __launch_bounds__(256) k3_out(
    const float* __restrict__ W1, const float* __restrict__ b1,
    const float* __restrict__ W2, const float* __restrict__ b2,
    const float* __restrict__ gamma, const float* __restrict__ beta,
    float* __restrict__ out)
{
    extern __shared__ char smc[];
    float* smf = (float*)smc;
    const uint32_t sb = smem_u32(smc);
    const int tid = threadIdx.x, lane = tid & 31, wid = tid >> 5;

    k3_prefetch(blockIdx.x, sb + K3_S0, tid);

    if (tid < 128) { smf[tid] = b1[tid];       smf[256 + tid] = gamma[tid]; }
    else           { smf[tid] = b2[tid - 128]; smf[256 + tid] = beta[tid - 128]; }
    w_split_to_smem(W1, smc, K3_W1H, tid);
    w_split_to_smem(W2, smc, K3_W2H, tid);

    const int mrow0 = (wid & 1) * 16;
    const int ncol0 = (wid >> 1) * 32;
    const uint32_t a_off = (uint32_t)((mrow0 + (lane & 7) + ((lane >> 3) & 1) * 8) * 272 + (lane >> 4) * 16);
    const uint32_t b_off = (uint32_t)((ncol0 + (lane >> 4) * 8 + (lane & 7)) * 272 + ((lane >> 3) & 1) * 16);
    const int r0 = lane >> 2, cs = (lane & 3) * 2;

    float4 gv, bvv;
    gv.x  = smf[256 + lane * 4 + 0]; gv.y  = smf[256 + lane * 4 + 1];
    gv.z  = smf[256 + lane * 4 + 2]; gv.w  = smf[256 + lane * 4 + 3];
    bvv.x = smf[384 + lane * 4 + 0]; bvv.y = smf[384 + lane * 4 + 1];
    bvv.z = smf[384 + lane * 4 + 2]; bvv.w = smf[384 + lane * 4 + 3];

    int cur = 0;
    for (int tile = blockIdx.x; tile < NTILES; tile += NSM) {
        int nt = tile + NSM;
        if (nt < NTILES) k3_prefetch(nt, sb + (cur ? K3_S0 : K3_S1), tid);
        else             CP_COMMIT();
        CP_WAIT1();
        __syncthreads();

        const uint32_t S = sb + (cur ? K3_S1 : K3_S0);
        float accU[4][4], accV[4][4];
        #pragma unroll
        for (int t = 0; t < 4; t++) {
            accU[t][0] = 0.f; accU[t][1] = 0.f; accU[t][2] = 0.f; accU[t][3] = 0.f;
            accV[t][0] = 0.f; accV[t][1] = 0.f; accV[t][2] = 0.f; accV[t][3] = 0.f;
        }

        #pragma unroll
        for (int pass = 0; pass < 3; pass++) {
            uint32_t Au = S + ((pass == 2) ? 8704u : 0u) + a_off;
            uint32_t Av = Au + 17408u;
            uint32_t B1 = sb + ((pass == 1) ? (K3_W1H + 34816) : K3_W1H) + b_off;
            uint32_t B2 = sb + ((pass == 1) ? (K3_W2H + 34816) : K3_W2H) + b_off;
            #pragma unroll
            for (int ks = 0; ks < 8; ks++) {
                uint32_t ka = ks * 32;
                uint32_t u0, u1, u2, u3, v0, v1, v2, v3;
                LDSM4(u0, u1, u2, u3, Au + ka);
                LDSM4(v0, v1, v2, v3, Av + ka);
                #pragma unroll
                for (int bt = 0; bt < 2; bt++) {
                    uint32_t c0, c1, c2, c3;
                    LDSM4(c0, c1, c2, c3, B1 + ka + bt * 4352);
                    MMA_BF16(accU[2 * bt],     u0, u1, u2, u3, c0, c1);
                    MMA_BF16(accU[2 * bt + 1], u0, u1, u2, u3, c2, c3);
                    uint32_t d0, d1, d2, d3;
                    LDSM4(d0, d1, d2, d3, B2 + ka + bt * 4352);
                    MMA_BF16(accV[2 * bt],     v0, v1, v2, v3, d0, d1);
                    MMA_BF16(accV[2 * bt + 1], v0, v1, v2, v3, d2, d3);
                }
            }
        }
        __syncthreads();

        float* hb = (float*)(smc + (cur ? K3_S1 : K3_S0));
        #pragma unroll
        for (int t = 0; t < 4; t++) {
            int col = ncol0 + t * 8 + cs;
            float b1v0 = smf[col], b1v1 = smf[col + 1];
            float b2v0 = smf[128 + col], b2v1 = smf[128 + col + 1];
            #pragma unroll
            for (int half = 0; half < 2; half++) {
                int row = mrow0 + r0 + half * 8;
                float t1a = accU[t][2 * half + 0] + b1v0;
                float t1b = accU[t][2 * half + 1] + b1v1;
                t1a = (t1a > 0.f) ? t1a : 0.01f * t1a;
                t1b = (t1b > 0.f) ? t1b : 0.01f * t1b;
                float t2a = accV[t][2 * half + 0] + b2v0;
                float t2b = accV[t][2 * half + 1] + b2v1;
                t2a = (t2a > 0.f) ? t2a : 0.01f * t2a;
                t2b = (t2b > 0.f) ? t2b : 0.01f * t2b;
                *(float2*)&hb[row * 132 + col] = make_float2(t1a + t2a, t1b + t2b);
            }
        }
        __syncthreads();

        int n0r = tile * 32;
        #pragma unroll
        for (int rr = 0; rr < 4; rr++) {
            int rw = wid * 4 + rr;
            int n = n0r + rw;
            float4 h = *(float4*)&hb[rw * 132 + lane * 4];
            float s  = h.x + h.y + h.z + h.w;
            float sq = h.x * h.x + h.y * h.y + h.z * h.z + h.w * h.w;
            #pragma unroll
            for (int o = 16; o >= 1; o >>= 1) {
                s  += __shfl_xor_sync(0xffffffffu, s,  o);
                sq += __shfl_xor_sync(0xffffffffu, sq, o);
            }
            float mu  = s * (1.0f / 128.0f);
            float var = sq * (1.0f / 128.0f) - mu * mu;
            float rs  = rsqrtf(var + 1e-5f);
            if (n < NN) {
                float4 o4;
                o4.x = (h.x - mu) * rs * gv.x + bvv.x;
                o4.y = (h.y - mu) * rs * gv.y + bvv.y;
                o4.z = (h.z - mu) * rs * gv.z + bvv.z;
                o4.w = (h.w - mu) * rs * gv.w + bvv.w;
                ((float4*)out)[(size_t)n * 32 + lane] = o4;
            }
        }
        __syncthreads();
        cur ^= 1;
    }
}

// ---------------------------------------------------------------------------
extern "C" void kernel_launch(void* const* d_in, const int* in_sizes, int n_in,
                              void* d_out, int out_size) {
    const float* x     = (const float*)d_in[0];
    const float* eh_in = (const float*)d_in[1];
    const float* et_in = (const float*)d_in[2];
    const int*   tidx  = (const int*)  d_in[3];
    const float* tw    = (const float*)d_in[4];
    const float* Wh    = (const float*)d_in[5];
    const float* bh    = (const float*)d_in[6];
    const float* Wt    = (const float*)d_in[7];
    const float* bt    = (const float*)d_in[8];
    const float* W1    = (const float*)d_in[9];
    const float* b1    = (const float*)d_in[10];
    const float* W2    = (const float*)d_in[11];
    const float* b2    = (const float*)d_in[12];
    const float* gamma = (const float*)d_in[13];
    const float* beta  = (const float*)d_in[14];
    float* out = (float*)d_out;

    cudaFuncSetAttribute(k1_proj, cudaFuncAttributeMaxDynamicSharedMemorySize, K1_SMEM);
    cudaFuncSetAttribute(k3_out,  cudaFuncAttributeMaxDynamicSharedMemorySize, K3_SMEM);

    k1_proj<<<NSM * 2, 256, K1_SMEM>>>(eh_in, et_in, Wh, bh, Wt, bt);
    k2_attn<<<NTILES, 256>>>(x, tidx, tw);
    k3_out<<<NSM, 256, K3_SMEM>>>(W1, b1, W2, b2, gamma, beta, out);
}

// round 11
// speedup vs baseline: 1.5578x; 1.0153x over previous
#include <cuda_runtime.h>
#include <cuda_bf16.h>
#include <cstdint>

#define NN     50000
#define DD     128
#define KNB    16
#define NTILES 1563    // ceil(NN/32)
#define NSM    148

// ------------------------- global scratch -----------------------------------
__device__ float         g_eh[(size_t)NN * DD];
__device__ float         g_et[(size_t)NN * DD];
__device__ __nv_bfloat16 g_uh[(size_t)NN * DD];
__device__ __nv_bfloat16 g_ul[(size_t)NN * DD];
__device__ __nv_bfloat16 g_vh[(size_t)NN * DD];
__device__ __nv_bfloat16 g_vl[(size_t)NN * DD];

// ------------------------- helpers ------------------------------------------
__device__ __forceinline__ uint32_t smem_u32(const void* p) {
    uint32_t a;
    asm("{ .reg .u64 t; cvta.to.shared.u64 t, %1; cvt.u32.u64 %0, t; }" : "=r"(a) : "l"(p));
    return a;
}
__device__ __forceinline__ uint32_t pack2(__nv_bfloat16 a, __nv_bfloat16 b) {
    __nv_bfloat162 t = __halves2bfloat162(a, b);
    return *(uint32_t*)&t;
}
__device__ __forceinline__ float tanh_hw(float z) {
    float r;
    asm("tanh.approx.f32 %0, %1;" : "=f"(r) : "f"(z));
    return r;
}
__device__ __forceinline__ void cpa16(uint32_t dst, const void* src) {
    asm volatile("cp.async.cg.shared.global [%0], [%1], 16;" :: "r"(dst), "l"(src));
}
#define CP_COMMIT() asm volatile("cp.async.commit_group;")
#define CP_WAIT1()  asm volatile("cp.async.wait_group 1;" ::: "memory")

#define LDSM4(r0, r1, r2, r3, addr) \
    asm volatile("ldmatrix.sync.aligned.m8n8.x4.shared.b16 {%0,%1,%2,%3}, [%4];" \
        : "=r"(r0), "=r"(r1), "=r"(r2), "=r"(r3) : "r"(addr))

#define MMA_BF16(d, a0, a1, a2, a3, b0, b1) \
    asm volatile("mma.sync.aligned.m16n8k16.row.col.f32.bf16.bf16.f32 " \
        "{%0,%1,%2,%3}, {%4,%5,%6,%7}, {%8,%9}, {%0,%1,%2,%3};" \
        : "+f"((d)[0]), "+f"((d)[1]), "+f"((d)[2]), "+f"((d)[3]) \
        : "r"(a0), "r"(a1), "r"(a2), "r"(a3), "r"(b0), "r"(b1))

__device__ __forceinline__ void split4(float4 f, uint2& hv, uint2& lv) {
    __nv_bfloat16 h0 = __float2bfloat16(f.x), h1 = __float2bfloat16(f.y);
    __nv_bfloat16 h2 = __float2bfloat16(f.z), h3 = __float2bfloat16(f.w);
    hv = make_uint2(pack2(h0, h1), pack2(h2, h3));
    lv = make_uint2(
        pack2(__float2bfloat16(f.x - __bfloat162float(h0)), __float2bfloat16(f.y - __bfloat162float(h1))),
        pack2(__float2bfloat16(f.z - __bfloat162float(h2)), __float2bfloat16(f.w - __bfloat162float(h3))));
}

// split a 128x128 fp32 weight matrix into hi/lo bf16 padded smem tiles
__device__ __forceinline__ void w_split_to_smem(const float* W, char* smc,
                                                int hbase, int tid) {
    const float4* W4 = (const float4*)W;
    #pragma unroll
    for (int j = 0; j < 16; j++) {
        int i = tid + j * 256;               // float4 index 0..4095
        int row = i >> 5, c4 = i & 31;
        uint2 hv, lv;
        split4(W4[i], hv, lv);
        uint32_t off = (uint32_t)(row * 272 + c4 * 8);
        *(uint2*)(smc + hbase + off)         = hv;
        *(uint2*)(smc + hbase + 34816 + off) = lv;
    }
}

// ------------------------- kernel 1: persistent projections (R5 shape) ------
// smem: [0,1024) biases; Wh hi/lo @1024/35840; Wt hi/lo @70656/105472;
//       A tiles: eh hi/lo @140288/148992, et hi/lo @157696/166400
#define K1_WHH 1024
#define K1_WTH 70656
#define K1_AEH 140288
#define K1_AET 157696
#define K1_SMEM 175104

__global__ void __launch_bounds__(256) k1_proj(
    const float* __restrict__ eh_in, const float* __restrict__ et_in,
    const float* __restrict__ Wh, const float* __restrict__ bh,
    const float* __restrict__ Wt, const float* __restrict__ bt)
{
    extern __shared__ char smc[];
    float* smf = (float*)smc;
    const uint32_t sb = smem_u32(smc);
    const int tid = threadIdx.x, lane = tid & 31, wid = tid >> 5;

    // prefetch first input tile into registers (overlaps weight conversion)
    float4 f[8];
    {
        int n0 = blockIdx.x * 32;
        #pragma unroll
        for (int j = 0; j < 8; j++) {
            int i = tid + j * 256;
            int inp = i >> 10, row = (i >> 5) & 31, c4 = i & 31;
            int n = n0 + row;
            f[j] = (n < NN) ? ((const float4*)(inp ? et_in : eh_in))[(size_t)n * 32 + c4]
                            : make_float4(0.f, 0.f, 0.f, 0.f);
        }
    }

    if (tid < 128) smf[tid] = bh[tid];
    else           smf[tid] = bt[tid - 128];
    w_split_to_smem(Wh, smc, K1_WHH, tid);
    w_split_to_smem(Wt, smc, K1_WTH, tid);
    __syncthreads();

    const int mat   = wid >> 2;
    const int nbase = (wid & 3) * 32;
    const uint32_t Ah = sb + (mat ? K1_AET : K1_AEH);
    const uint32_t Al = Ah + 8704;
    const uint32_t Bh = sb + (mat ? K1_WTH : K1_WHH);
    const uint32_t Bl = Bh + 34816;
    const uint32_t a_off = (uint32_t)(((lane & 7) + ((lane >> 3) & 1) * 8) * 272 + (lane >> 4) * 16);
    const uint32_t b_off = (uint32_t)((nbase + (lane >> 4) * 8 + (lane & 7)) * 272 + ((lane >> 3) & 1) * 16);
    float* outp = mat ? g_et : g_eh;
    const float* bias = smf + mat * 128;
    const int r0 = lane >> 2, cs = (lane & 3) * 2;

    for (int tile = blockIdx.x; tile < NTILES; tile += NSM) {
        // convert current tile regs -> A smem tiles
        #pragma unroll
        for (int j = 0; j < 8; j++) {
            int i = tid + j * 256;
            int inp = i >> 10, row = (i >> 5) & 31, c4 = i & 31;
            uint2 hv, lv;
            split4(f[j], hv, lv);
            uint32_t base = inp ? K1_AET : K1_AEH;
            uint32_t off = (uint32_t)(row * 272 + c4 * 8);
            *(uint2*)(smc + base + off)        = hv;
            *(uint2*)(smc + base + 8704 + off) = lv;
        }
        // prefetch next tile
        {
            int nt = tile + NSM;
            if (nt < NTILES) {
                int n0 = nt * 32;
                #pragma unroll
                for (int j = 0; j < 8; j++) {
                    int i = tid + j * 256;
                    int inp = i >> 10, row = (i >> 5) & 31, c4 = i & 31;
                    int n = n0 + row;
                    f[j] = (n < NN) ? ((const float4*)(inp ? et_in : eh_in))[(size_t)n * 32 + c4]
                                    : make_float4(0.f, 0.f, 0.f, 0.f);
                }
            }
        }
        __syncthreads();

        float acc[2][4][4];
        #pragma unroll
        for (int mt = 0; mt < 2; mt++)
            #pragma unroll
            for (int t = 0; t < 4; t++) {
                acc[mt][t][0] = 0.f; acc[mt][t][1] = 0.f; acc[mt][t][2] = 0.f; acc[mt][t][3] = 0.f;
            }

        #pragma unroll
        for (int pass = 0; pass < 3; pass++) {
            uint32_t A = ((pass == 2) ? Al : Ah) + a_off;
            uint32_t B = ((pass == 1) ? Bl : Bh) + b_off;
            #pragma unroll
            for (int ks = 0; ks < 8; ks++) {
                uint32_t ka = ks * 32;
                uint32_t a0, a1, a2, a3, a4, a5, a6, a7;
                LDSM4(a0, a1, a2, a3, A + ka);
                LDSM4(a4, a5, a6, a7, A + ka + 16 * 272);
                #pragma unroll
                for (int bt2 = 0; bt2 < 2; bt2++) {
                    uint32_t b0, b1, b2, b3;
                    LDSM4(b0, b1, b2, b3, B + ka + bt2 * 4352);
                    MMA_BF16(acc[0][2 * bt2],     a0, a1, a2, a3, b0, b1);
                    MMA_BF16(acc[0][2 * bt2 + 1], a0, a1, a2, a3, b2, b3);
                    MMA_BF16(acc[1][2 * bt2],     a4, a5, a6, a7, b0, b1);
                    MMA_BF16(acc[1][2 * bt2 + 1], a4, a5, a6, a7, b2, b3);
                }
            }
        }

        // epilogue: bias + fp32 store
        int n0 = tile * 32;
        #pragma unroll
        for (int mt = 0; mt < 2; mt++) {
            #pragma unroll
            for (int t = 0; t < 4; t++) {
                int col = nbase + t * 8 + cs;
                float bv0 = bias[col], bv1 = bias[col + 1];
                int na = n0 + mt * 16 + r0, nb2 = na + 8;
                if (na < NN)
                    *(float2*)&outp[(size_t)na * DD + col] =
                        make_float2(acc[mt][t][0] + bv0, acc[mt][t][1] + bv1);
                if (nb2 < NN)
                    *(float2*)&outp[(size_t)nb2 * DD + col] =
                        make_float2(acc[mt][t][2] + bv0, acc[mt][t][3] + bv1);
            }
        }
        __syncthreads();   // all gemm reads done before next conv overwrite
    }
}

// ------------------------- kernel 2: attention (hw tanh, depth-3 gather) ----
__global__ void __launch_bounds__(256, 3) k2_attn(
    const float* __restrict__ x, const int* __restrict__ tidx,
    const float* __restrict__ tw)
{
    const int tid = threadIdx.x, lane = tid & 31, wid = tid >> 5;
    const int n0 = blockIdx.x * 32;

    #pragma unroll 1
    for (int rr = 0; rr < 4; rr++) {
        const int n = n0 + wid * 4 + rr;
        if (n >= NN) continue;
        float4 eh = ((const float4*)g_eh)[(size_t)n * 32 + lane];
        float4 xr = ((const float4*)x)[(size_t)n * 32 + lane];

        int   ids[KNB];
        float ps[KNB];
        {
            const int4*   ip = (const int4*)(tidx + (size_t)n * KNB);
            const float4* pp = (const float4*)(tw + (size_t)n * KNB);
            #pragma unroll
            for (int j = 0; j < 4; j++) {
                int4 I = ip[j]; float4 P = pp[j];
                ids[4 * j + 0] = I.x; ids[4 * j + 1] = I.y;
                ids[4 * j + 2] = I.z; ids[4 * j + 3] = I.w;
                ps[4 * j + 0] = P.x; ps[4 * j + 1] = P.y;
                ps[4 * j + 2] = P.z; ps[4 * j + 3] = P.w;
            }
        }

        float a0 = 0.f, a1 = 0.f, a2 = 0.f, a3 = 0.f, s = 0.f;
        float4 nv0 = ((const float4*)g_et)[(size_t)ids[0] * 32 + lane];
        float4 nv1 = ((const float4*)g_et)[(size_t)ids[1] * 32 + lane];
        float4 nv2 = ((const float4*)g_et)[(size_t)ids[2] * 32 + lane];
        #pragma unroll
        for (int k = 0; k < KNB; k++) {
            float4 cur = nv0;
            nv0 = nv1;
            nv1 = nv2;
            if (k + 3 < KNB)
                nv2 = ((const float4*)g_et)[(size_t)ids[k + 3] * 32 + lane];
            float p = ps[k], q = 2.0f - p;
            float part;
            part  = cur.x * tanh_hw(fmaf(q, eh.x, p * cur.x));
            part += cur.y * tanh_hw(fmaf(q, eh.y, p * cur.y));
            part += cur.z * tanh_hw(fmaf(q, eh.z, p * cur.z));
            part += cur.w * tanh_hw(fmaf(q, eh.w, p * cur.w));
            #pragma unroll
            for (int o = 16; o >= 1; o >>= 1)
                part += __shfl_xor_sync(0xffffffffu, part, o);
            float e = __expf(part);   // |part| bounded ~25; safe without shift
            a0 = fmaf(e, cur.x, a0);
            a1 = fmaf(e, cur.y, a1);
            a2 = fmaf(e, cur.z, a2);
            a3 = fmaf(e, cur.w, a3);
            s += e;
        }
        float inv = __fdividef(1.0f, s);
        float e0 = a0 * inv, e1 = a1 * inv, e2 = a2 * inv, e3 = a3 * inv;

        float4 u = make_float4(xr.x + e0, xr.y + e1, xr.z + e2, xr.w + e3);
        float4 v = make_float4(xr.x * e0, xr.y * e1, xr.z * e2, xr.w * e3);
        uint2 uhv, ulv, vhv, vlv;
        split4(u, uhv, ulv);
        split4(v, vhv, vlv);
        ((uint2*)(g_uh + (size_t)n * DD))[lane] = uhv;
        ((uint2*)(g_ul + (size_t)n * DD))[lane] = ulv;
        ((uint2*)(g_vh + (size_t)n * DD))[lane] = vhv;
        ((uint2*)(g_vl + (size_t)n * DD))[lane] = vlv;
    }
}

// ------------------------- kernel 3: persistent GEMMs + LN ------------------
#define K3_W1H 2048
#define K3_W2H 71680
#define K3_S0  141312
#define K3_S1  176128
#define K3_SMEM 210944

__device__ __forceinline__ void k3_prefetch(int tile, uint32_t stage, int tid) {
    int n0 = tile * 32;
    #pragma unroll
    for (int j = 0; j < 8; j++) {
        int i = tid + j * 256;
        int arr = i >> 9, row = (i >> 4) & 31, c = i & 15;
        int n = n0 + row;
        if (n < NN) {
            const __nv_bfloat16* src = (arr == 0) ? g_uh : (arr == 1) ? g_ul
                                      : (arr == 2) ? g_vh : g_vl;
            cpa16(stage + (uint32_t)(arr * 8704 + row * 272 + c * 16),
                  (const char*)src + ((size_t)n * 256 + (size_t)c * 16));
        }
    }
    CP_COMMIT();
}

__global__ void __launch_bounds__(256) k3_out(
    const float* __restrict__ W1, const float* __restrict__ b1,
    const float* __restrict__ W2, const float* __restrict__ b2,
    const float* __restrict__ gamma, const float* __restrict__ beta,
    float* __restrict__ out)
{
    extern __shared__ char smc[];
    float* smf = (float*)smc;
    const uint32_t sb = smem_u32(smc);
    const int tid = threadIdx.x, lane = tid & 31, wid = tid >> 5;

    k3_prefetch(blockIdx.x, sb + K3_S0, tid);

    if (tid < 128) { smf[tid] = b1[tid];       smf[256 + tid] = gamma[tid]; }
    else           { smf[tid] = b2[tid - 128]; smf[256 + tid] = beta[tid - 128]; }
    w_split_to_smem(W1, smc, K3_W1H, tid);
    w_split_to_smem(W2, smc, K3_W2H, tid);

    const int mrow0 = (wid & 1) * 16;
    const int ncol0 = (wid >> 1) * 32;
    const uint32_t a_off = (uint32_t)((mrow0 + (lane & 7) + ((lane >> 3) & 1) * 8) * 272 + (lane >> 4) * 16);
    const uint32_t b_off = (uint32_t)((ncol0 + (lane >> 4) * 8 + (lane & 7)) * 272 + ((lane >> 3) & 1) * 16);
    const int r0 = lane >> 2, cs = (lane & 3) * 2;

    float4 gv, bvv;
    gv.x  = smf[256 + lane * 4 + 0]; gv.y  = smf[256 + lane * 4 + 1];
    gv.z  = smf[256 + lane * 4 + 2]; gv.w  = smf[256 + lane * 4 + 3];
    bvv.x = smf[384 + lane * 4 + 0]; bvv.y = smf[384 + lane * 4 + 1];
    bvv.z = smf[384 + lane * 4 + 2]; bvv.w = smf[384 + lane * 4 + 3];

    int cur = 0;
    for (int tile = blockIdx.x; tile < NTILES; tile += NSM) {
        int nt = tile + NSM;
        if (nt < NTILES) k3_prefetch(nt, sb + (cur ? K3_S0 : K3_S1), tid);
        else             CP_COMMIT();
        CP_WAIT1();
        __syncthreads();

        const uint32_t S = sb + (cur ? K3_S1 : K3_S0);
        float accU[4][4], accV[4][4];
        #pragma unroll
        for (int t = 0; t < 4; t++) {
            accU[t][0] = 0.f; accU[t][1] = 0.f; accU[t][2] = 0.f; accU[t][3] = 0.f;
            accV[t][0] = 0.f; accV[t][1] = 0.f; accV[t][2] = 0.f; accV[t][3] = 0.f;
        }

        #pragma unroll
        for (int pass = 0; pass < 3; pass++) {
            uint32_t Au = S + ((pass == 2) ? 8704u : 0u) + a_off;
            uint32_t Av = Au + 17408u;
            uint32_t B1 = sb + ((pass == 1) ? (K3_W1H + 34816) : K3_W1H) + b_off;
            uint32_t B2 = sb + ((pass == 1) ? (K3_W2H + 34816) : K3_W2H) + b_off;
            #pragma unroll
            for (int ks = 0; ks < 8; ks++) {
                uint32_t ka = ks * 32;
                uint32_t u0, u1, u2, u3, v0, v1, v2, v3;
                LDSM4(u0, u1, u2, u3, Au + ka);
                LDSM4(v0, v1, v2, v3, Av + ka);
                #pragma unroll
                for (int bt = 0; bt < 2; bt++) {
                    uint32_t c0, c1, c2, c3;
                    LDSM4(c0, c1, c2, c3, B1 + ka + bt * 4352);
                    MMA_BF16(accU[2 * bt],     u0, u1, u2, u3, c0, c1);
                    MMA_BF16(accU[2 * bt + 1], u0, u1, u2, u3, c2, c3);
                    uint32_t d0, d1, d2, d3;
                    LDSM4(d0, d1, d2, d3, B2 + ka + bt * 4352);
                    MMA_BF16(accV[2 * bt],     v0, v1, v2, v3, d0, d1);
                    MMA_BF16(accV[2 * bt + 1], v0, v1, v2, v3, d2, d3);
                }
            }
        }
        __syncthreads();

        float* hb = (float*)(smc + (cur ? K3_S1 : K3_S0));
        #pragma unroll
        for (int t = 0; t < 4; t++) {
            int col = ncol0 + t * 8 + cs;
            float b1v0 = smf[col], b1v1 = smf[col + 1];
            float b2v0 = smf[128 + col], b2v1 = smf[128 + col + 1];
            #pragma unroll
            for (int half = 0; half < 2; half++) {
                int row = mrow0 + r0 + half * 8;
                float t1a = accU[t][2 * half + 0] + b1v0;
                float t1b = accU[t][2 * half + 1] + b1v1;
                t1a = (t1a > 0.f) ? t1a : 0.01f * t1a;
                t1b = (t1b > 0.f) ? t1b : 0.01f * t1b;
                float t2a = accV[t][2 * half + 0] + b2v0;
                float t2b = accV[t][2 * half + 1] + b2v1;
                t2a = (t2a > 0.f) ? t2a : 0.01f * t2a;
                t2b = (t2b > 0.f) ? t2b : 0.01f * t2b;
                *(float2*)&hb[row * 132 + col] = make_float2(t1a + t2a, t1b + t2b);
            }
        }
        __syncthreads();

        int n0r = tile * 32;
        #pragma unroll
        for (int rr = 0; rr < 4; rr++) {
            int rw = wid * 4 + rr;
            int n = n0r + rw;
            float4 h = *(float4*)&hb[rw * 132 + lane * 4];
            float s  = h.x + h.y + h.z + h.w;
            float sq = h.x * h.x + h.y * h.y + h.z * h.z + h.w * h.w;
            #pragma unroll
            for (int o = 16; o >= 1; o >>= 1) {
                s  += __shfl_xor_sync(0xffffffffu, s,  o);
                sq += __shfl_xor_sync(0xffffffffu, sq, o);
            }
            float mu  = s * (1.0f / 128.0f);
            float var = sq * (1.0f / 128.0f) - mu * mu;
            float rs  = rsqrtf(var + 1e-5f);
            if (n < NN) {
                float4 o4;
                o4.x = (h.x - mu) * rs * gv.x + bvv.x;
                o4.y = (h.y - mu) * rs * gv.y + bvv.y;
                o4.z = (h.z - mu) * rs * gv.z + bvv.z;
                o4.w = (h.w - mu) * rs * gv.w + bvv.w;
                ((float4*)out)[(size_t)n * 32 + lane] = o4;
            }
        }
        __syncthreads();
        cur ^= 1;
    }
}

// ---------------------------------------------------------------------------
extern "C" void kernel_launch(void* const* d_in, const int* in_sizes, int n_in,
                              void* d_out, int out_size) {
    const float* x     = (const float*)d_in[0];
    const float* eh_in = (const float*)d_in[1];
    const float* et_in = (const float*)d_in[2];
    const int*   tidx  = (const int*)  d_in[3];
    const float* tw    = (const float*)d_in[4];
    const float* Wh    = (const float*)d_in[5];
    const float* bh    = (const float*)d_in[6];
    const float* Wt    = (const float*)d_in[7];
    const float* bt    = (const float*)d_in[8];
    const float* W1    = (const float*)d_in[9];
    const float* b1    = (const float*)d_in[10];
    const float* W2    = (const float*)d_in[11];
    const float* b2    = (const float*)d_in[12];
    const float* gamma = (const float*)d_in[13];
    const float* beta  = (const float*)d_in[14];
    float* out = (float*)d_out;

    cudaFuncSetAttribute(k1_proj, cudaFuncAttributeMaxDynamicSharedMemorySize, K1_SMEM);
    cudaFuncSetAttribute(k3_out,  cudaFuncAttributeMaxDynamicSharedMemorySize, K3_SMEM);

    k1_proj<<<NSM, 256, K1_SMEM>>>(eh_in, et_in, Wh, bh, Wt, bt);
    k2_attn<<<NTILES, 256>>>(x, tidx, tw);
    k3_out<<<NSM, 256, K3_SMEM>>>(W1, b1, W2, b2, gamma, beta, out);
}

// round 12
// speedup vs baseline: 1.5820x; 1.0155x over previous
#include <cuda_runtime.h>
#include <cuda_bf16.h>
#include <cuda_fp16.h>
#include <cstdint>

#define NN     50000
#define DD     128
#define KNB    16
#define NTILES 1563    // ceil(NN/32)
#define NSM    148

// ------------------------- global scratch -----------------------------------
__device__ float         g_eh[(size_t)NN * DD];
__device__ __half        g_et[(size_t)NN * DD];     // fp16: gather traffic halved
__device__ __nv_bfloat16 g_uh[(size_t)NN * DD];
__device__ __nv_bfloat16 g_ul[(size_t)NN * DD];
__device__ __nv_bfloat16 g_vh[(size_t)NN * DD];
__device__ __nv_bfloat16 g_vl[(size_t)NN * DD];

// ------------------------- helpers ------------------------------------------
__device__ __forceinline__ uint32_t smem_u32(const void* p) {
    uint32_t a;
    asm("{ .reg .u64 t; cvta.to.shared.u64 t, %1; cvt.u32.u64 %0, t; }" : "=r"(a) : "l"(p));
    return a;
}
__device__ __forceinline__ uint32_t pack2(__nv_bfloat16 a, __nv_bfloat16 b) {
    __nv_bfloat162 t = __halves2bfloat162(a, b);
    return *(uint32_t*)&t;
}
__device__ __forceinline__ float tanh_hw(float z) {
    float r;
    asm("tanh.approx.f32 %0, %1;" : "=f"(r) : "f"(z));
    return r;
}
__device__ __forceinline__ void cpa16(uint32_t dst, const void* src) {
    asm volatile("cp.async.cg.shared.global [%0], [%1], 16;" :: "r"(dst), "l"(src));
}
#define CP_COMMIT() asm volatile("cp.async.commit_group;")
#define CP_WAIT1()  asm volatile("cp.async.wait_group 1;" ::: "memory")

#define LDSM4(r0, r1, r2, r3, addr) \
    asm volatile("ldmatrix.sync.aligned.m8n8.x4.shared.b16 {%0,%1,%2,%3}, [%4];" \
        : "=r"(r0), "=r"(r1), "=r"(r2), "=r"(r3) : "r"(addr))

#define MMA_BF16(d, a0, a1, a2, a3, b0, b1) \
    asm volatile("mma.sync.aligned.m16n8k16.row.col.f32.bf16.bf16.f32 " \
        "{%0,%1,%2,%3}, {%4,%5,%6,%7}, {%8,%9}, {%0,%1,%2,%3};" \
        : "+f"((d)[0]), "+f"((d)[1]), "+f"((d)[2]), "+f"((d)[3]) \
        : "r"(a0), "r"(a1), "r"(a2), "r"(a3), "r"(b0), "r"(b1))

__device__ __forceinline__ void split4(float4 f, uint2& hv, uint2& lv) {
    __nv_bfloat16 h0 = __float2bfloat16(f.x), h1 = __float2bfloat16(f.y);
    __nv_bfloat16 h2 = __float2bfloat16(f.z), h3 = __float2bfloat16(f.w);
    hv = make_uint2(pack2(h0, h1), pack2(h2, h3));
    lv = make_uint2(
        pack2(__float2bfloat16(f.x - __bfloat162float(h0)), __float2bfloat16(f.y - __bfloat162float(h1))),
        pack2(__float2bfloat16(f.z - __bfloat162float(h2)), __float2bfloat16(f.w - __bfloat162float(h3))));
}

// split a 128x128 fp32 weight matrix into hi/lo bf16 padded smem tiles
__device__ __forceinline__ void w_split_to_smem(const float* W, char* smc,
                                                int hbase, int tid) {
    const float4* W4 = (const float4*)W;
    #pragma unroll
    for (int j = 0; j < 16; j++) {
        int i = tid + j * 256;               // float4 index 0..4095
        int row = i >> 5, c4 = i & 31;
        uint2 hv, lv;
        split4(W4[i], hv, lv);
        uint32_t off = (uint32_t)(row * 272 + c4 * 8);
        *(uint2*)(smc + hbase + off)         = hv;
        *(uint2*)(smc + hbase + 34816 + off) = lv;
    }
}

// ------------------------- kernel 1: persistent projections (R5 shape) ------
#define K1_WHH 1024
#define K1_WTH 70656
#define K1_AEH 140288
#define K1_AET 157696
#define K1_SMEM 175104

__global__ void __launch_bounds__(256) k1_proj(
    const float* __restrict__ eh_in, const float* __restrict__ et_in,
    const float* __restrict__ Wh, const float* __restrict__ bh,
    const float* __restrict__ Wt, const float* __restrict__ bt)
{
    extern __shared__ char smc[];
    float* smf = (float*)smc;
    const uint32_t sb = smem_u32(smc);
    const int tid = threadIdx.x, lane = tid & 31, wid = tid >> 5;

    // prefetch first input tile into registers (overlaps weight conversion)
    float4 f[8];
    {
        int n0 = blockIdx.x * 32;
        #pragma unroll
        for (int j = 0; j < 8; j++) {
            int i = tid + j * 256;
            int inp = i >> 10, row = (i >> 5) & 31, c4 = i & 31;
            int n = n0 + row;
            f[j] = (n < NN) ? ((const float4*)(inp ? et_in : eh_in))[(size_t)n * 32 + c4]
                            : make_float4(0.f, 0.f, 0.f, 0.f);
        }
    }

    if (tid < 128) smf[tid] = bh[tid];
    else           smf[tid] = bt[tid - 128];
    w_split_to_smem(Wh, smc, K1_WHH, tid);
    w_split_to_smem(Wt, smc, K1_WTH, tid);
    __syncthreads();

    const int mat   = wid >> 2;
    const int nbase = (wid & 3) * 32;
    const uint32_t Ah = sb + (mat ? K1_AET : K1_AEH);
    const uint32_t Al = Ah + 8704;
    const uint32_t Bh = sb + (mat ? K1_WTH : K1_WHH);
    const uint32_t Bl = Bh + 34816;
    const uint32_t a_off = (uint32_t)(((lane & 7) + ((lane >> 3) & 1) * 8) * 272 + (lane >> 4) * 16);
    const uint32_t b_off = (uint32_t)((nbase + (lane >> 4) * 8 + (lane & 7)) * 272 + ((lane >> 3) & 1) * 16);
    const float* bias = smf + mat * 128;
    const int r0 = lane >> 2, cs = (lane & 3) * 2;

    for (int tile = blockIdx.x; tile < NTILES; tile += NSM) {
        // convert current tile regs -> A smem tiles
        #pragma unroll
        for (int j = 0; j < 8; j++) {
            int i = tid + j * 256;
            int inp = i >> 10, row = (i >> 5) & 31, c4 = i & 31;
            uint2 hv, lv;
            split4(f[j], hv, lv);
            uint32_t base = inp ? K1_AET : K1_AEH;
            uint32_t off = (uint32_t)(row * 272 + c4 * 8);
            *(uint2*)(smc + base + off)        = hv;
            *(uint2*)(smc + base + 8704 + off) = lv;
        }
        // prefetch next tile
        {
            int nt = tile + NSM;
            if (nt < NTILES) {
                int n0 = nt * 32;
                #pragma unroll
                for (int j = 0; j < 8; j++) {
                    int i = tid + j * 256;
                    int inp = i >> 10, row = (i >> 5) & 31, c4 = i & 31;
                    int n = n0 + row;
                    f[j] = (n < NN) ? ((const float4*)(inp ? et_in : eh_in))[(size_t)n * 32 + c4]
                                    : make_float4(0.f, 0.f, 0.f, 0.f);
                }
            }
        }
        __syncthreads();

        float acc[2][4][4];
        #pragma unroll
        for (int mt = 0; mt < 2; mt++)
            #pragma unroll
            for (int t = 0; t < 4; t++) {
                acc[mt][t][0] = 0.f; acc[mt][t][1] = 0.f; acc[mt][t][2] = 0.f; acc[mt][t][3] = 0.f;
            }

        #pragma unroll
        for (int pass = 0; pass < 3; pass++) {
            uint32_t A = ((pass == 2) ? Al : Ah) + a_off;
            uint32_t B = ((pass == 1) ? Bl : Bh) + b_off;
            #pragma unroll
            for (int ks = 0; ks < 8; ks++) {
                uint32_t ka = ks * 32;
                uint32_t a0, a1, a2, a3, a4, a5, a6, a7;
                LDSM4(a0, a1, a2, a3, A + ka);
                LDSM4(a4, a5, a6, a7, A + ka + 16 * 272);
                #pragma unroll
                for (int bt2 = 0; bt2 < 2; bt2++) {
                    uint32_t b0, b1, b2, b3;
                    LDSM4(b0, b1, b2, b3, B + ka + bt2 * 4352);
                    MMA_BF16(acc[0][2 * bt2],     a0, a1, a2, a3, b0, b1);
                    MMA_BF16(acc[0][2 * bt2 + 1], a0, a1, a2, a3, b2, b3);
                    MMA_BF16(acc[1][2 * bt2],     a4, a5, a6, a7, b0, b1);
                    MMA_BF16(acc[1][2 * bt2 + 1], a4, a5, a6, a7, b2, b3);
                }
            }
        }

        // epilogue: bias + store (e_h fp32, e_t fp16)
        int n0 = tile * 32;
        #pragma unroll
        for (int mt = 0; mt < 2; mt++) {
            #pragma unroll
            for (int t = 0; t < 4; t++) {
                int col = nbase + t * 8 + cs;
                float bv0 = bias[col], bv1 = bias[col + 1];
                int na = n0 + mt * 16 + r0, nb2 = na + 8;
                if (mat == 0) {
                    if (na < NN)
                        *(float2*)&g_eh[(size_t)na * DD + col] =
                            make_float2(acc[mt][t][0] + bv0, acc[mt][t][1] + bv1);
                    if (nb2 < NN)
                        *(float2*)&g_eh[(size_t)nb2 * DD + col] =
                            make_float2(acc[mt][t][2] + bv0, acc[mt][t][3] + bv1);
                } else {
                    if (na < NN)
                        *(__half2*)&g_et[(size_t)na * DD + col] =
                            __floats2half2_rn(acc[mt][t][0] + bv0, acc[mt][t][1] + bv1);
                    if (nb2 < NN)
                        *(__half2*)&g_et[(size_t)nb2 * DD + col] =
                            __floats2half2_rn(acc[mt][t][2] + bv0, acc[mt][t][3] + bv1);
                }
            }
        }
        __syncthreads();   // all gemm reads done before next conv overwrite
    }
}

// ------------------------- kernel 2: attention (fp16 gather) ----------------
__global__ void __launch_bounds__(256, 3) k2_attn(
    const float* __restrict__ x, const int* __restrict__ tidx,
    const float* __restrict__ tw)
{
    const int tid = threadIdx.x, lane = tid & 31, wid = tid >> 5;
    const int n0 = blockIdx.x * 32;

    #pragma unroll 1
    for (int rr = 0; rr < 4; rr++) {
        const int n = n0 + wid * 4 + rr;
        if (n >= NN) continue;
        float4 eh = ((const float4*)g_eh)[(size_t)n * 32 + lane];
        float4 xr = ((const float4*)x)[(size_t)n * 32 + lane];

        int   ids[KNB];
        float ps[KNB];
        {
            const int4*   ip = (const int4*)(tidx + (size_t)n * KNB);
            const float4* pp = (const float4*)(tw + (size_t)n * KNB);
            #pragma unroll
            for (int j = 0; j < 4; j++) {
                int4 I = ip[j]; float4 P = pp[j];
                ids[4 * j + 0] = I.x; ids[4 * j + 1] = I.y;
                ids[4 * j + 2] = I.z; ids[4 * j + 3] = I.w;
                ps[4 * j + 0] = P.x; ps[4 * j + 1] = P.y;
                ps[4 * j + 2] = P.z; ps[4 * j + 3] = P.w;
            }
        }

        // online softmax accumulation, depth-3 fp16 gather pipeline
        float a0 = 0.f, a1 = 0.f, a2 = 0.f, a3 = 0.f, s = 0.f;
        const uint2* et2 = (const uint2*)g_et;   // 4 halves per uint2
        uint2 nv0 = et2[(size_t)ids[0] * 32 + lane];
        uint2 nv1 = et2[(size_t)ids[1] * 32 + lane];
        uint2 nv2 = et2[(size_t)ids[2] * 32 + lane];
        #pragma unroll
        for (int k = 0; k < KNB; k++) {
            uint2 raw = nv0;
            nv0 = nv1;
            nv1 = nv2;
            if (k + 3 < KNB)
                nv2 = et2[(size_t)ids[k + 3] * 32 + lane];
            float2 f01 = __half22float2(*(__half2*)&raw.x);
            float2 f23 = __half22float2(*(__half2*)&raw.y);
            float p = ps[k], q = 2.0f - p;
            float part;
            part  = f01.x * tanh_hw(fmaf(q, eh.x, p * f01.x));
            part += f01.y * tanh_hw(fmaf(q, eh.y, p * f01.y));
            part += f23.x * tanh_hw(fmaf(q, eh.z, p * f23.x));
            part += f23.y * tanh_hw(fmaf(q, eh.w, p * f23.y));
            #pragma unroll
            for (int o = 16; o >= 1; o >>= 1)
                part += __shfl_xor_sync(0xffffffffu, part, o);
            float e = __expf(part);   // |part| bounded ~25; safe without shift
            a0 = fmaf(e, f01.x, a0);
            a1 = fmaf(e, f01.y, a1);
            a2 = fmaf(e, f23.x, a2);
            a3 = fmaf(e, f23.y, a3);
            s += e;
        }
        float inv = __fdividef(1.0f, s);
        float e0 = a0 * inv, e1 = a1 * inv, e2 = a2 * inv, e3 = a3 * inv;

        float4 u = make_float4(xr.x + e0, xr.y + e1, xr.z + e2, xr.w + e3);
        float4 v = make_float4(xr.x * e0, xr.y * e1, xr.z * e2, xr.w * e3);
        uint2 uhv, ulv, vhv, vlv;
        split4(u, uhv, ulv);
        split4(v, vhv, vlv);
        ((uint2*)(g_uh + (size_t)n * DD))[lane] = uhv;
        ((uint2*)(g_ul + (size_t)n * DD))[lane] = ulv;
        ((uint2*)(g_vh + (size_t)n * DD))[lane] = vhv;
        ((uint2*)(g_vl + (size_t)n * DD))[lane] = vlv;
    }
}

// ------------------------- kernel 3: persistent GEMMs + LN ------------------
#define K3_W1H 2048
#define K3_W2H 71680
#define K3_S0  141312
#define K3_S1  176128
#define K3_SMEM 210944

__device__ __forceinline__ void k3_prefetch(int tile, uint32_t stage, int tid) {
    int n0 = tile * 32;
    #pragma unroll
    for (int j = 0; j < 8; j++) {
        int i = tid + j * 256;
        int arr = i >> 9, row = (i >> 4) & 31, c = i & 15;
        int n = n0 + row;
        if (n < NN) {
            const __nv_bfloat16* src = (arr == 0) ? g_uh : (arr == 1) ? g_ul
                                      : (arr == 2) ? g_vh : g_vl;
            cpa16(stage + (uint32_t)(arr * 8704 + row * 272 + c * 16),
                  (const char*)src + ((size_t)n * 256 + (size_t)c * 16));
        }
    }
    CP_COMMIT();
}

__global__ void __launch_bounds__(256) k3_out(
    const float* __restrict__ W1, const float* __restrict__ b1,
    const float* __restrict__ W2, const float* __restrict__ b2,
    const float* __restrict__ gamma, const float* __restrict__ beta,
    float* __restrict__ out)
{
    extern __shared__ char smc[];
    float* smf = (float*)smc;
    const uint32_t sb = smem_u32(smc);
    const int tid = threadIdx.x, lane = tid & 31, wid = tid >> 5;

    k3_prefetch(blockIdx.x, sb + K3_S0, tid);

    if (tid < 128) { smf[tid] = b1[tid];       smf[256 + tid] = gamma[tid]; }
    else           { smf[tid] = b2[tid - 128]; smf[256 + tid] = beta[tid - 128]; }
    w_split_to_smem(W1, smc, K3_W1H, tid);
    w_split_to_smem(W2, smc, K3_W2H, tid);

    const int mrow0 = (wid & 1) * 16;
    const int ncol0 = (wid >> 1) * 32;
    const uint32_t a_off = (uint32_t)((mrow0 + (lane & 7) + ((lane >> 3) & 1) * 8) * 272 + (lane >> 4) * 16);
    const uint32_t b_off = (uint32_t)((ncol0 + (lane >> 4) * 8 + (lane & 7)) * 272 + ((lane >> 3) & 1) * 16);
    const int r0 = lane >> 2, cs = (lane & 3) * 2;

    float4 gv, bvv;
    gv.x  = smf[256 + lane * 4 + 0]; gv.y  = smf[256 + lane * 4 + 1];
    gv.z  = smf[256 + lane * 4 + 2]; gv.w  = smf[256 + lane * 4 + 3];
    bvv.x = smf[384 + lane * 4 + 0]; bvv.y = smf[384 + lane * 4 + 1];
    bvv.z = smf[384 + lane * 4 + 2]; bvv.w = smf[384 + lane * 4 + 3];

    int cur = 0;
    for (int tile = blockIdx.x; tile < NTILES; tile += NSM) {
        int nt = tile + NSM;
        if (nt < NTILES) k3_prefetch(nt, sb + (cur ? K3_S0 : K3_S1), tid);
        else             CP_COMMIT();
        CP_WAIT1();
        __syncthreads();

        const uint32_t S = sb + (cur ? K3_S1 : K3_S0);
        float accU[4][4], accV[4][4];
        #pragma unroll
        for (int t = 0; t < 4; t++) {
            accU[t][0] = 0.f; accU[t][1] = 0.f; accU[t][2] = 0.f; accU[t][3] = 0.f;
            accV[t][0] = 0.f; accV[t][1] = 0.f; accV[t][2] = 0.f; accV[t][3] = 0.f;
        }

        #pragma unroll
        for (int pass = 0; pass < 3; pass++) {
            uint32_t Au = S + ((pass == 2) ? 8704u : 0u) + a_off;
            uint32_t Av = Au + 17408u;
            uint32_t B1 = sb + ((pass == 1) ? (K3_W1H + 34816) : K3_W1H) + b_off;
            uint32_t B2 = sb + ((pass == 1) ? (K3_W2H + 34816) : K3_W2H) + b_off;
            #pragma unroll
            for (int ks = 0; ks < 8; ks++) {
                uint32_t ka = ks * 32;
                uint32_t u0, u1, u2, u3, v0, v1, v2, v3;
                LDSM4(u0, u1, u2, u3, Au + ka);
                LDSM4(v0, v1, v2, v3, Av + ka);
                #pragma unroll
                for (int bt = 0; bt < 2; bt++) {
                    uint32_t c0, c1, c2, c3;
                    LDSM4(c0, c1, c2, c3, B1 + ka + bt * 4352);
                    MMA_BF16(accU[2 * bt],     u0, u1, u2, u3, c0, c1);
                    MMA_BF16(accU[2 * bt + 1], u0, u1, u2, u3, c2, c3);
                    uint32_t d0, d1, d2, d3;
                    LDSM4(d0, d1, d2, d3, B2 + ka + bt * 4352);
                    MMA_BF16(accV[2 * bt],     v0, v1, v2, v3, d0, d1);
                    MMA_BF16(accV[2 * bt + 1], v0, v1, v2, v3, d2, d3);
                }
            }
        }
        __syncthreads();

        float* hb = (float*)(smc + (cur ? K3_S1 : K3_S0));
        #pragma unroll
        for (int t = 0; t < 4; t++) {
            int col = ncol0 + t * 8 + cs;
            float b1v0 = smf[col], b1v1 = smf[col + 1];
            float b2v0 = smf[128 + col], b2v1 = smf[128 + col + 1];
            #pragma unroll
            for (int half = 0; half < 2; half++) {
                int row = mrow0 + r0 + half * 8;
                float t1a = accU[t][2 * half + 0] + b1v0;
                float t1b = accU[t][2 * half + 1] + b1v1;
                t1a = (t1a > 0.f) ? t1a : 0.01f * t1a;
                t1b = (t1b > 0.f) ? t1b : 0.01f * t1b;
                float t2a = accV[t][2 * half + 0] + b2v0;
                float t2b = accV[t][2 * half + 1] + b2v1;
                t2a = (t2a > 0.f) ? t2a : 0.01f * t2a;
                t2b = (t2b > 0.f) ? t2b : 0.01f * t2b;
                *(float2*)&hb[row * 132 + col] = make_float2(t1a + t2a, t1b + t2b);
            }
        }
        __syncthreads();

        int n0r = tile * 32;
        #pragma unroll
        for (int rr = 0; rr < 4; rr++) {
            int rw = wid * 4 + rr;
            int n = n0r + rw;
            float4 h = *(float4*)&hb[rw * 132 + lane * 4];
            float s  = h.x + h.y + h.z + h.w;
            float sq = h.x * h.x + h.y * h.y + h.z * h.z + h.w * h.w;
            #pragma unroll
            for (int o = 16; o >= 1; o >>= 1) {
                s  += __shfl_xor_sync(0xffffffffu, s,  o);
                sq += __shfl_xor_sync(0xffffffffu, sq, o);
            }
            float mu  = s * (1.0f / 128.0f);
            float var = sq * (1.0f / 128.0f) - mu * mu;
            float rs  = rsqrtf(var + 1e-5f);
            if (n < NN) {
                float4 o4;
                o4.x = (h.x - mu) * rs * gv.x + bvv.x;
                o4.y = (h.y - mu) * rs * gv.y + bvv.y;
                o4.z = (h.z - mu) * rs * gv.z + bvv.z;
                o4.w = (h.w - mu) * rs * gv.w + bvv.w;
                ((float4*)out)[(size_t)n * 32 + lane] = o4;
            }
        }
        __syncthreads();
        cur ^= 1;
    }
}

// ---------------------------------------------------------------------------
extern "C" void kernel_launch(void* const* d_in, const int* in_sizes, int n_in,
                              void* d_out, int out_size) {
    const float* x     = (const float*)d_in[0];
    const float* eh_in = (const float*)d_in[1];
    const float* et_in = (const float*)d_in[2];
    const int*   tidx  = (const int*)  d_in[3];
    const float* tw    = (const float*)d_in[4];
    const float* Wh    = (const float*)d_in[5];
    const float* bh    = (const float*)d_in[6];
    const float* Wt    = (const float*)d_in[7];
    const float* bt    = (const float*)d_in[8];
    const float* W1    = (const float*)d_in[9];
    const float* b1    = (const float*)d_in[10];
    const float* W2    = (const float*)d_in[11];
    const float* b2    = (const float*)d_in[12];
    const float* gamma = (const float*)d_in[13];
    const float* beta  = (const float*)d_in[14];
    float* out = (float*)d_out;

    cudaFuncSetAttribute(k1_proj, cudaFuncAttributeMaxDynamicSharedMemorySize, K1_SMEM);
    cudaFuncSetAttribute(k3_out,  cudaFuncAttributeMaxDynamicSharedMemorySize, K3_SMEM);

    k1_proj<<<NSM, 256, K1_SMEM>>>(eh_in, et_in, Wh, bh, Wt, bt);
    k2_attn<<<NTILES, 256>>>(x, tidx, tw);
    k3_out<<<NSM, 256, K3_SMEM>>>(W1, b1, W2, b2, gamma, beta, out);
}

// round 17
// speedup vs baseline: 1.6089x; 1.0170x over previous
#include <cuda_runtime.h>
#include <cuda_bf16.h>
#include <cuda_fp16.h>
#include <cstdint>

#define NN     50000
#define DD     128
#define KNB    16
#define NTILES 1563    // ceil(NN/32)
#define NSM    148

// ------------------------- global scratch -----------------------------------
__device__ __half        g_eh[(size_t)NN * DD];     // fp16: feeds tanh ARG only
__device__ __half        g_et[(size_t)NN * DD];     // fp16: gather traffic halved
__device__ __nv_bfloat16 g_uh[(size_t)NN * DD];
__device__ __nv_bfloat16 g_ul[(size_t)NN * DD];
__device__ __nv_bfloat16 g_vh[(size_t)NN * DD];
__device__ __nv_bfloat16 g_vl[(size_t)NN * DD];

// ------------------------- helpers ------------------------------------------
__device__ __forceinline__ uint32_t smem_u32(const void* p) {
    uint32_t a;
    asm("{ .reg .u64 t; cvta.to.shared.u64 t, %1; cvt.u32.u64 %0, t; }" : "=r"(a) : "l"(p));
    return a;
}
__device__ __forceinline__ uint32_t pack2(__nv_bfloat16 a, __nv_bfloat16 b) {
    __nv_bfloat162 t = __halves2bfloat162(a, b);
    return *(uint32_t*)&t;
}
__device__ __forceinline__ float tanh_hw(float z) {
    float r;
    asm("tanh.approx.f32 %0, %1;" : "=f"(r) : "f"(z));
    return r;
}
__device__ __forceinline__ void cpa16(uint32_t dst, const void* src) {
    asm volatile("cp.async.cg.shared.global [%0], [%1], 16;" :: "r"(dst), "l"(src));
}
#define CP_COMMIT() asm volatile("cp.async.commit_group;")
#define CP_WAIT1()  asm volatile("cp.async.wait_group 1;" ::: "memory")

#define LDSM4(r0, r1, r2, r3, addr) \
    asm volatile("ldmatrix.sync.aligned.m8n8.x4.shared.b16 {%0,%1,%2,%3}, [%4];" \
        : "=r"(r0), "=r"(r1), "=r"(r2), "=r"(r3) : "r"(addr))

#define MMA_BF16(d, a0, a1, a2, a3, b0, b1) \
    asm volatile("mma.sync.aligned.m16n8k16.row.col.f32.bf16.bf16.f32 " \
        "{%0,%1,%2,%3}, {%4,%5,%6,%7}, {%8,%9}, {%0,%1,%2,%3};" \
        : "+f"((d)[0]), "+f"((d)[1]), "+f"((d)[2]), "+f"((d)[3]) \
        : "r"(a0), "r"(a1), "r"(a2), "r"(a3), "r"(b0), "r"(b1))

__device__ __forceinline__ void split4(float4 f, uint2& hv, uint2& lv) {
    __nv_bfloat16 h0 = __float2bfloat16(f.x), h1 = __float2bfloat16(f.y);
    __nv_bfloat16 h2 = __float2bfloat16(f.z), h3 = __float2bfloat16(f.w);
    hv = make_uint2(pack2(h0, h1), pack2(h2, h3));
    lv = make_uint2(
        pack2(__float2bfloat16(f.x - __bfloat162float(h0)), __float2bfloat16(f.y - __bfloat162float(h1))),
        pack2(__float2bfloat16(f.z - __bfloat162float(h2)), __float2bfloat16(f.w - __bfloat162float(h3))));
}

// split a 128x128 fp32 weight matrix into hi/lo bf16 padded smem tiles
__device__ __forceinline__ void w_split_to_smem(const float* W, char* smc,
                                                int hbase, int tid) {
    const float4* W4 = (const float4*)W;
    #pragma unroll
    for (int j = 0; j < 16; j++) {
        int i = tid + j * 256;
        int row = i >> 5, c4 = i & 31;
        uint2 hv, lv;
        split4(W4[i], hv, lv);
        uint32_t off = (uint32_t)(row * 272 + c4 * 8);
        *(uint2*)(smc + hbase + off)         = hv;
        *(uint2*)(smc + hbase + 34816 + off) = lv;
    }
}

// ------------------------- kernel 1: persistent projections (R5 shape) ------
#define K1_WHH 1024
#define K1_WTH 70656
#define K1_AEH 140288
#define K1_AET 157696
#define K1_SMEM 175104

__global__ void __launch_bounds__(256) k1_proj(
    const float* __restrict__ eh_in, const float* __restrict__ et_in,
    const float* __restrict__ Wh, const float* __restrict__ bh,
    const float* __restrict__ Wt, const float* __restrict__ bt)
{
    extern __shared__ char smc[];
    float* smf = (float*)smc;
    const uint32_t sb = smem_u32(smc);
    const int tid = threadIdx.x, lane = tid & 31, wid = tid >> 5;

    // prefetch first input tile into registers (overlaps weight conversion)
    float4 f[8];
    {
        int n0 = blockIdx.x * 32;
        #pragma unroll
        for (int j = 0; j < 8; j++) {
            int i = tid + j * 256;
            int inp = i >> 10, row = (i >> 5) & 31, c4 = i & 31;
            int n = n0 + row;
            f[j] = (n < NN) ? ((const float4*)(inp ? et_in : eh_in))[(size_t)n * 32 + c4]
                            : make_float4(0.f, 0.f, 0.f, 0.f);
        }
    }

    if (tid < 128) smf[tid] = bh[tid];
    else           smf[tid] = bt[tid - 128];
    w_split_to_smem(Wh, smc, K1_WHH, tid);
    w_split_to_smem(Wt, smc, K1_WTH, tid);
    __syncthreads();

    const int mat   = wid >> 2;
    const int nbase = (wid & 3) * 32;
    const uint32_t Ah = sb + (mat ? K1_AET : K1_AEH);
    const uint32_t Al = Ah + 8704;
    const uint32_t Bh = sb + (mat ? K1_WTH : K1_WHH);
    const uint32_t Bl = Bh + 34816;
    const uint32_t a_off = (uint32_t)(((lane & 7) + ((lane >> 3) & 1) * 8) * 272 + (lane >> 4) * 16);
    const uint32_t b_off = (uint32_t)((nbase + (lane >> 4) * 8 + (lane & 7)) * 272 + ((lane >> 3) & 1) * 16);
    __half* outp = mat ? g_et : g_eh;
    const float* bias = smf + mat * 128;
    const int r0 = lane >> 2, cs = (lane & 3) * 2;

    for (int tile = blockIdx.x; tile < NTILES; tile += NSM) {
        // convert current tile regs -> A smem tiles
        #pragma unroll
        for (int j = 0; j < 8; j++) {
            int i = tid + j * 256;
            int inp = i >> 10, row = (i >> 5) & 31, c4 = i & 31;
            uint2 hv, lv;
            split4(f[j], hv, lv);
            uint32_t base = inp ? K1_AET : K1_AEH;
            uint32_t off = (uint32_t)(row * 272 + c4 * 8);
            *(uint2*)(smc + base + off)        = hv;
            *(uint2*)(smc + base + 8704 + off) = lv;
        }
        // prefetch next tile
        {
            int nt = tile + NSM;
            if (nt < NTILES) {
                int n0 = nt * 32;
                #pragma unroll
                for (int j = 0; j < 8; j++) {
                    int i = tid + j * 256;
                    int inp = i >> 10, row = (i >> 5) & 31, c4 = i & 31;
                    int n = n0 + row;
                    f[j] = (n < NN) ? ((const float4*)(inp ? et_in : eh_in))[(size_t)n * 32 + c4]
                                    : make_float4(0.f, 0.f, 0.f, 0.f);
                }
            }
        }
        __syncthreads();

        float acc[2][4][4];
        #pragma unroll
        for (int mt = 0; mt < 2; mt++)
            #pragma unroll
            for (int t = 0; t < 4; t++) {
                acc[mt][t][0] = 0.f; acc[mt][t][1] = 0.f; acc[mt][t][2] = 0.f; acc[mt][t][3] = 0.f;
            }

        #pragma unroll
        for (int pass = 0; pass < 3; pass++) {
            uint32_t A = ((pass == 2) ? Al : Ah) + a_off;
            uint32_t B = ((pass == 1) ? Bl : Bh) + b_off;
            #pragma unroll
            for (int ks = 0; ks < 8; ks++) {
                uint32_t ka = ks * 32;
                uint32_t a0, a1, a2, a3, a4, a5, a6, a7;
                LDSM4(a0, a1, a2, a3, A + ka);
                LDSM4(a4, a5, a6, a7, A + ka + 16 * 272);
                #pragma unroll
                for (int bt2 = 0; bt2 < 2; bt2++) {
                    uint32_t b0, b1, b2, b3;
                    LDSM4(b0, b1, b2, b3, B + ka + bt2 * 4352);
                    MMA_BF16(acc[0][2 * bt2],     a0, a1, a2, a3, b0, b1);
                    MMA_BF16(acc[0][2 * bt2 + 1], a0, a1, a2, a3, b2, b3);
                    MMA_BF16(acc[1][2 * bt2],     a4, a5, a6, a7, b0, b1);
                    MMA_BF16(acc[1][2 * bt2 + 1], a4, a5, a6, a7, b2, b3);
                }
            }
        }

        // epilogue: bias + fp16 store (both outputs)
        int n0 = tile * 32;
        #pragma unroll
        for (int mt = 0; mt < 2; mt++) {
            #pragma unroll
            for (int t = 0; t < 4; t++) {
                int col = nbase + t * 8 + cs;
                float bv0 = bias[col], bv1 = bias[col + 1];
                int na = n0 + mt * 16 + r0, nb2 = na + 8;
                if (na < NN)
                    *(__half2*)&outp[(size_t)na * DD + col] =
                        __floats2half2_rn(acc[mt][t][0] + bv0, acc[mt][t][1] + bv1);
                if (nb2 < NN)
                    *(__half2*)&outp[(size_t)nb2 * DD + col] =
                        __floats2half2_rn(acc[mt][t][2] + bv0, acc[mt][t][3] + bv1);
            }
        }
        __syncthreads();   // all gemm reads done before next conv overwrite
    }
}

// ------------------------- kernel 2: attention (fp32 gate, fp16 gathers) ----
__global__ void __launch_bounds__(256, 3) k2_attn(
    const float* __restrict__ x, const int* __restrict__ tidx,
    const float* __restrict__ tw)
{
    const int tid = threadIdx.x, lane = tid & 31, wid = tid >> 5;
    const int n0 = blockIdx.x * 32;

    #pragma unroll 1
    for (int rr = 0; rr < 4; rr++) {
        const int n = n0 + wid * 4 + rr;
        if (n >= NN) continue;
        uint2 ehr = ((const uint2*)g_eh)[(size_t)n * 32 + lane];
        float2 eh01 = __half22float2(*(__half2*)&ehr.x);
        float2 eh23 = __half22float2(*(__half2*)&ehr.y);
        float4 xr = ((const float4*)x)[(size_t)n * 32 + lane];

        int   ids[KNB];
        float ps[KNB];
        {
            const int4*   ip = (const int4*)(tidx + (size_t)n * KNB);
            const float4* pp = (const float4*)(tw + (size_t)n * KNB);
            #pragma unroll
            for (int j = 0; j < 4; j++) {
                int4 I = ip[j]; float4 P = pp[j];
                ids[4 * j + 0] = I.x; ids[4 * j + 1] = I.y;
                ids[4 * j + 2] = I.z; ids[4 * j + 3] = I.w;
                ps[4 * j + 0] = P.x; ps[4 * j + 1] = P.y;
                ps[4 * j + 2] = P.z; ps[4 * j + 3] = P.w;
            }
        }

        // online softmax accumulation, depth-3 fp16 gather pipeline.
        // Gate + logits + softmax + accumulation all in fp32 (budget-critical).
        float a0 = 0.f, a1 = 0.f, a2 = 0.f, a3 = 0.f, s = 0.f;
        const uint2* et2 = (const uint2*)g_et;
        uint2 nv0 = et2[(size_t)ids[0] * 32 + lane];
        uint2 nv1 = et2[(size_t)ids[1] * 32 + lane];
        uint2 nv2 = et2[(size_t)ids[2] * 32 + lane];
        #pragma unroll
        for (int k = 0; k < KNB; k++) {
            uint2 raw = nv0;
            nv0 = nv1;
            nv1 = nv2;
            if (k + 3 < KNB)
                nv2 = et2[(size_t)ids[k + 3] * 32 + lane];
            float2 f01 = __half22float2(*(__half2*)&raw.x);
            float2 f23 = __half22float2(*(__half2*)&raw.y);
            float p = ps[k], q = 2.0f - p;
            float part;
            part  = f01.x * tanh_hw(fmaf(q, eh01.x, p * f01.x));
            part += f01.y * tanh_hw(fmaf(q, eh01.y, p * f01.y));
            part += f23.x * tanh_hw(fmaf(q, eh23.x, p * f23.x));
            part += f23.y * tanh_hw(fmaf(q, eh23.y, p * f23.y));
            #pragma unroll
            for (int o = 16; o >= 1; o >>= 1)
                part += __shfl_xor_sync(0xffffffffu, part, o);
            float e = __expf(part);   // |part| bounded ~25; safe without shift
            a0 = fmaf(e, f01.x, a0);
            a1 = fmaf(e, f01.y, a1);
            a2 = fmaf(e, f23.x, a2);
            a3 = fmaf(e, f23.y, a3);
            s += e;
        }
        float inv = __fdividef(1.0f, s);
        float e0 = a0 * inv, e1 = a1 * inv, e2 = a2 * inv, e3 = a3 * inv;

        float4 u = make_float4(xr.x + e0, xr.y + e1, xr.z + e2, xr.w + e3);
        float4 v = make_float4(xr.x * e0, xr.y * e1, xr.z * e2, xr.w * e3);
        uint2 uhv, ulv, vhv, vlv;
        split4(u, uhv, ulv);
        split4(v, vhv, vlv);
        ((uint2*)(g_uh + (size_t)n * DD))[lane] = uhv;
        ((uint2*)(g_ul + (size_t)n * DD))[lane] = ulv;
        ((uint2*)(g_vh + (size_t)n * DD))[lane] = vhv;
        ((uint2*)(g_vl + (size_t)n * DD))[lane] = vlv;
    }
}

// ------------------------- kernel 3: persistent GEMMs + LN ------------------
#define K3_W1H 2048
#define K3_W2H 71680
#define K3_S0  141312
#define K3_S1  176128
#define K3_SMEM 210944

__device__ __forceinline__ void k3_prefetch(int tile, uint32_t stage, int tid) {
    int n0 = tile * 32;
    #pragma unroll
    for (int j = 0; j < 8; j++) {
        int i = tid + j * 256;
        int arr = i >> 9, row = (i >> 4) & 31, c = i & 15;
        int n = n0 + row;
        if (n < NN) {
            const __nv_bfloat16* src = (arr == 0) ? g_uh : (arr == 1) ? g_ul
                                      : (arr == 2) ? g_vh : g_vl;
            cpa16(stage + (uint32_t)(arr * 8704 + row * 272 + c * 16),
                  (const char*)src + ((size_t)n * 256 + (size_t)c * 16));
        }
    }
    CP_COMMIT();
}

__global__ void __launch_bounds__(256) k3_out(
    const float* __restrict__ W1, const float* __restrict__ b1,
    const float* __restrict__ W2, const float* __restrict__ b2,
    const float* __restrict__ gamma, const float* __restrict__ beta,
    float* __restrict__ out)
{
    extern __shared__ char smc[];
    float* smf = (float*)smc;
    const uint32_t sb = smem_u32(smc);
    const int tid = threadIdx.x, lane = tid & 31, wid = tid >> 5;

    k3_prefetch(blockIdx.x, sb + K3_S0, tid);

    if (tid < 128) { smf[tid] = b1[tid];       smf[256 + tid] = gamma[tid]; }
    else           { smf[tid] = b2[tid - 128]; smf[256 + tid] = beta[tid - 128]; }
    w_split_to_smem(W1, smc, K3_W1H, tid);
    w_split_to_smem(W2, smc, K3_W2H, tid);

    const int mrow0 = (wid & 1) * 16;
    const int ncol0 = (wid >> 1) * 32;
    const uint32_t a_off = (uint32_t)((mrow0 + (lane & 7) + ((lane >> 3) & 1) * 8) * 272 + (lane >> 4) * 16);
    const uint32_t b_off = (uint32_t)((ncol0 + (lane >> 4) * 8 + (lane & 7)) * 272 + ((lane >> 3) & 1) * 16);
    const int r0 = lane >> 2, cs = (lane & 3) * 2;

    float4 gv, bvv;
    gv.x  = smf[256 + lane * 4 + 0]; gv.y  = smf[256 + lane * 4 + 1];
    gv.z  = smf[256 + lane * 4 + 2]; gv.w  = smf[256 + lane * 4 + 3];
    bvv.x = smf[384 + lane * 4 + 0]; bvv.y = smf[384 + lane * 4 + 1];
    bvv.z = smf[384 + lane * 4 + 2]; bvv.w = smf[384 + lane * 4 + 3];

    int cur = 0;
    for (int tile = blockIdx.x; tile < NTILES; tile += NSM) {
        int nt = tile + NSM;
        if (nt < NTILES) k3_prefetch(nt, sb + (cur ? K3_S0 : K3_S1), tid);
        else             CP_COMMIT();
        CP_WAIT1();
        __syncthreads();

        const uint32_t S = sb + (cur ? K3_S1 : K3_S0);
        float accU[4][4], accV[4][4];
        #pragma unroll
        for (int t = 0; t < 4; t++) {
            accU[t][0] = 0.f; accU[t][1] = 0.f; accU[t][2] = 0.f; accU[t][3] = 0.f;
            accV[t][0] = 0.f; accV[t][1] = 0.f; accV[t][2] = 0.f; accV[t][3] = 0.f;
        }

        #pragma unroll
        for (int pass = 0; pass < 3; pass++) {
            uint32_t Au = S + ((pass == 2) ? 8704u : 0u) + a_off;
            uint32_t Av = Au + 17408u;
            uint32_t B1 = sb + ((pass == 1) ? (K3_W1H + 34816) : K3_W1H) + b_off;
            uint32_t B2 = sb + ((pass == 1) ? (K3_W2H + 34816) : K3_W2H) + b_off;
            #pragma unroll
            for (int ks = 0; ks < 8; ks++) {
                uint32_t ka = ks * 32;
                uint32_t u0, u1, u2, u3, v0, v1, v2, v3;
                LDSM4(u0, u1, u2, u3, Au + ka);
                LDSM4(v0, v1, v2, v3, Av + ka);
                #pragma unroll
                for (int bt = 0; bt < 2; bt++) {
                    uint32_t c0, c1, c2, c3;
                    LDSM4(c0, c1, c2, c3, B1 + ka + bt * 4352);
                    MMA_BF16(accU[2 * bt],     u0, u1, u2, u3, c0, c1);
                    MMA_BF16(accU[2 * bt + 1], u0, u1, u2, u3, c2, c3);
                    uint32_t d0, d1, d2, d3;
                    LDSM4(d0, d1, d2, d3, B2 + ka + bt * 4352);
                    MMA_BF16(accV[2 * bt],     v0, v1, v2, v3, d0, d1);
                    MMA_BF16(accV[2 * bt + 1], v0, v1, v2, v3, d2, d3);
                }
            }
        }
        __syncthreads();

        float* hb = (float*)(smc + (cur ? K3_S1 : K3_S0));
        #pragma unroll
        for (int t = 0; t < 4; t++) {
            int col = ncol0 + t * 8 + cs;
            float b1v0 = smf[col], b1v1 = smf[col + 1];
            float b2v0 = smf[128 + col], b2v1 = smf[128 + col + 1];
            #pragma unroll
            for (int half = 0; half < 2; half++) {
                int row = mrow0 + r0 + half * 8;
                float t1a = accU[t][2 * half + 0] + b1v0;
                float t1b = accU[t][2 * half + 1] + b1v1;
                t1a = (t1a > 0.f) ? t1a : 0.01f * t1a;
                t1b = (t1b > 0.f) ? t1b : 0.01f * t1b;
                float t2a = accV[t][2 * half + 0] + b2v0;
                float t2b = accV[t][2 * half + 1] + b2v1;
                t2a = (t2a > 0.f) ? t2a : 0.01f * t2a;
                t2b = (t2b > 0.f) ? t2b : 0.01f * t2b;
                *(float2*)&hb[row * 132 + col] = make_float2(t1a + t2a, t1b + t2b);
            }
        }
        __syncthreads();

        int n0r = tile * 32;
        #pragma unroll
        for (int rr = 0; rr < 4; rr++) {
            int rw = wid * 4 + rr;
            int n = n0r + rw;
            float4 h = *(float4*)&hb[rw * 132 + lane * 4];
            float s  = h.x + h.y + h.z + h.w;
            float sq = h.x * h.x + h.y * h.y + h.z * h.z + h.w * h.w;
            #pragma unroll
            for (int o = 16; o >= 1; o >>= 1) {
                s  += __shfl_xor_sync(0xffffffffu, s,  o);
                sq += __shfl_xor_sync(0xffffffffu, sq, o);
            }
            float mu  = s * (1.0f / 128.0f);
            float var = sq * (1.0f / 128.0f) - mu * mu;
            float rs  = rsqrtf(var + 1e-5f);
            if (n < NN) {
                float4 o4;
                o4.x = (h.x - mu) * rs * gv.x + bvv.x;
                o4.y = (h.y - mu) * rs * gv.y + bvv.y;
                o4.z = (h.z - mu) * rs * gv.z + bvv.z;
                o4.w = (h.w - mu) * rs * gv.w + bvv.w;
                ((float4*)out)[(size_t)n * 32 + lane] = o4;
            }
        }
        __syncthreads();
        cur ^= 1;
    }
}

// ---------------------------------------------------------------------------
extern "C" void kernel_launch(void* const* d_in, const int* in_sizes, int n_in,
                              void* d_out, int out_size) {
    const float* x     = (const float*)d_in[0];
    const float* eh_in = (const float*)d_in[1];
    const float* et_in = (const float*)d_in[2];
    const int*   tidx  = (const int*)  d_in[3];
    const float* tw    = (const float*)d_in[4];
    const float* Wh    = (const float*)d_in[5];
    const float* bh    = (const float*)d_in[6];
    const float* Wt    = (const float*)d_in[7];
    const float* bt    = (const float*)d_in[8];
    const float* W1    = (const float*)d_in[9];
    const float* b1    = (const float*)d_in[10];
    const float* W2    = (const float*)d_in[11];
    const float* b2    = (const float*)d_in[12];
    const float* gamma = (const float*)d_in[13];
    const float* beta  = (const float*)d_in[14];
    float* out = (float*)d_out;

    cudaFuncSetAttribute(k1_proj, cudaFuncAttributeMaxDynamicSharedMemorySize, K1_SMEM);
    cudaFuncSetAttribute(k3_out,  cudaFuncAttributeMaxDynamicSharedMemorySize, K3_SMEM);

    k1_proj<<<NSM, 256, K1_SMEM>>>(eh_in, et_in, Wh, bh, Wt, bt);
    k2_attn<<<NTILES, 256>>>(x, tidx, tw);
    k3_out<<<NSM, 256, K3_SMEM>>>(W1, b1, W2, b2, gamma, beta, out);
}